// round 1
// baseline (speedup 1.0000x reference)
#include <cuda_runtime.h>
#include <cuda_bf16.h>
#include <cstdint>

// Problem constants
#define BATCH 2
#define SEQ 2048
#define HID 3584
#define NH 28
#define NKV 4
#define HD 128
#define NREP 7
#define M_ROWS (BATCH * SEQ)           // 4096
#define KV_HID (NKV * HD)              // 512
#define SCALE_F 0.08838834764831845f   // 128^-0.5

// Scratch (device globals; allocation is forbidden)
__device__ float g_Q[(size_t)M_ROWS * HID];      // [B,S,28,128]
__device__ float g_K[(size_t)M_ROWS * KV_HID];   // [B,S,4,128]
__device__ float g_V[(size_t)M_ROWS * KV_HID];   // [B,S,4,128]
__device__ float g_A[(size_t)M_ROWS * HID];      // attention out [B,S,28,128]

// ---------------------------------------------------------------------------
// SGEMM: C[M,N] = A[M,K] @ W[N,K]^T + bias   (A,W row-major, K contiguous)
// 128x128 tile, BK=8, 256 threads, 8x8 microtile per thread.
// ---------------------------------------------------------------------------
__global__ void __launch_bounds__(256) sgemm_nt_kernel(
    const float* __restrict__ A, const float* __restrict__ W,
    const float* __restrict__ bias, float* __restrict__ C,
    int M, int N, int K)
{
    __shared__ float As[8][128];
    __shared__ float Bs[8][128];

    const int bm = blockIdx.y * 128;
    const int bn = blockIdx.x * 128;
    const int tid = threadIdx.x;
    const int lrow = tid >> 1;          // 0..127
    const int lcol = (tid & 1) << 2;    // 0 or 4
    const int tx = tid & 15;
    const int ty = tid >> 4;

    const float* Ap = A + (size_t)(bm + lrow) * K + lcol;
    const float* Wp = W + (size_t)(bn + lrow) * K + lcol;

    float acc[8][8];
#pragma unroll
    for (int i = 0; i < 8; i++)
#pragma unroll
        for (int j = 0; j < 8; j++) acc[i][j] = 0.f;

    for (int k0 = 0; k0 < K; k0 += 8) {
        float4 av = *(const float4*)(Ap + k0);
        float4 wv = *(const float4*)(Wp + k0);
        __syncthreads();   // previous iteration's readers done
        As[lcol + 0][lrow] = av.x; As[lcol + 1][lrow] = av.y;
        As[lcol + 2][lrow] = av.z; As[lcol + 3][lrow] = av.w;
        Bs[lcol + 0][lrow] = wv.x; Bs[lcol + 1][lrow] = wv.y;
        Bs[lcol + 2][lrow] = wv.z; Bs[lcol + 3][lrow] = wv.w;
        __syncthreads();
#pragma unroll
        for (int kk = 0; kk < 8; kk++) {
            float ar[8], br[8];
            *(float4*)&ar[0] = *(const float4*)&As[kk][ty * 8];
            *(float4*)&ar[4] = *(const float4*)&As[kk][ty * 8 + 4];
            *(float4*)&br[0] = *(const float4*)&Bs[kk][tx * 8];
            *(float4*)&br[4] = *(const float4*)&Bs[kk][tx * 8 + 4];
#pragma unroll
            for (int i = 0; i < 8; i++)
#pragma unroll
                for (int j = 0; j < 8; j++)
                    acc[i][j] += ar[i] * br[j];
        }
    }

#pragma unroll
    for (int i = 0; i < 8; i++) {
        const int row = bm + ty * 8 + i;
#pragma unroll
        for (int j0 = 0; j0 < 8; j0 += 4) {
            const int col = bn + tx * 8 + j0;
            float4 v;
            if (bias) {
                v.x = acc[i][j0 + 0] + bias[col + 0];
                v.y = acc[i][j0 + 1] + bias[col + 1];
                v.z = acc[i][j0 + 2] + bias[col + 2];
                v.w = acc[i][j0 + 3] + bias[col + 3];
            } else {
                v.x = acc[i][j0 + 0]; v.y = acc[i][j0 + 1];
                v.z = acc[i][j0 + 2]; v.w = acc[i][j0 + 3];
            }
            *(float4*)&C[(size_t)row * N + col] = v;
        }
    }
}

// ---------------------------------------------------------------------------
// RoPE in-place on Q and K.
// idx bits: d(6) | h(5: 0-27 = Q heads, 28-31 = K heads) | s(11) | b(1)
// ---------------------------------------------------------------------------
__global__ void rope_kernel(float* __restrict__ Q, float* __restrict__ K,
                            const float* __restrict__ cosT,
                            const float* __restrict__ sinT)
{
    const int idx = blockIdx.x * blockDim.x + threadIdx.x;
    const int d = idx & 63;
    const int h = (idx >> 6) & 31;
    const int s = (idx >> 11) & 2047;
    const int b = idx >> 22;

    const float c1 = cosT[s * 128 + d];
    const float s1 = sinT[s * 128 + d];
    const float c2 = cosT[s * 128 + d + 64];
    const float s2 = sinT[s * 128 + d + 64];

    float* p;
    if (h < 28) p = Q + (((size_t)b * SEQ + s) * NH + h) * HD;
    else        p = K + (((size_t)b * SEQ + s) * NKV + (h - 28)) * HD;

    const float x1 = p[d];
    const float x2 = p[d + 64];
    p[d]      = x1 * c1 - x2 * s1;
    p[d + 64] = x2 * c2 + x1 * s2;
}

// ---------------------------------------------------------------------------
// Causal flash attention (fp32).
// Grid: (S/64, NH, B). 256 threads: thread = (row 0..63, quad 0..3).
// Each thread owns one q-row and a strided quarter of the 128 dims:
//   dims of (quad, n, t) = (4n + quad)*4 + t, n in [0,8), t in [0,4)
// (strided assignment -> 4 quads read 4 consecutive 16B chunks = conflict-free)
// ---------------------------------------------------------------------------
__global__ void __launch_bounds__(256) flash_kernel(
    const float* __restrict__ Q, const float* __restrict__ K,
    const float* __restrict__ V, float* __restrict__ O)
{
    extern __shared__ float sm[];
    float* Ks = sm;               // 64*128
    float* Vs = sm + 64 * 128;    // 64*128
    float* Ps = sm + 2 * 64 * 128;// 64*64

    const int qb = blockIdx.x, h = blockIdx.y, b = blockIdx.z;
    const int kvh = h / NREP;
    const int tid = threadIdx.x;
    const int row = tid >> 2;
    const int quad = tid & 3;
    const int qrow = qb * 64 + row;

    // q row into registers, prescaled
    float qreg[32];
    {
        const float* qp = Q + (((size_t)b * SEQ + qrow) * NH + h) * HD;
#pragma unroll
        for (int n = 0; n < 8; n++) {
            float4 v = *(const float4*)(qp + (4 * n + quad) * 4);
            qreg[4 * n + 0] = v.x * SCALE_F;
            qreg[4 * n + 1] = v.y * SCALE_F;
            qreg[4 * n + 2] = v.z * SCALE_F;
            qreg[4 * n + 3] = v.w * SCALE_F;
        }
    }
    float oacc[32];
#pragma unroll
    for (int i = 0; i < 32; i++) oacc[i] = 0.f;
    float m_i = -1e30f, l_i = 0.f;

    const float* kbase = K + (((size_t)b * SEQ) * NKV + kvh) * HD;
    const float* vbase = V + (((size_t)b * SEQ) * NKV + kvh) * HD;

    for (int kb = 0; kb <= qb; kb++) {
        __syncthreads();
        // cooperative load of K,V blocks (64 rows x 128)
        {
            const float* kp = kbase + (size_t)kb * 64 * KV_HID;
            const float* vp = vbase + (size_t)kb * 64 * KV_HID;
#pragma unroll
            for (int it = 0; it < 8; it++) {
                const int idx = tid + it * 256;   // float4 index 0..2047
                const int r = idx >> 5;
                const int c = (idx & 31) * 4;
                *(float4*)(Ks + r * 128 + c) = *(const float4*)(kp + (size_t)r * KV_HID + c);
                *(float4*)(Vs + r * 128 + c) = *(const float4*)(vp + (size_t)r * KV_HID + c);
            }
        }
        __syncthreads();

        const int jmax = (kb == qb) ? (row + 1) : 64;
        float mblk = -1e30f;

        // pass A: raw scores -> Ps, track block max
        for (int j = 0; j < 64; j++) {
            float acc = 0.f;
            const float* kr = Ks + j * 128;
#pragma unroll
            for (int n = 0; n < 8; n++) {
                float4 kv4 = *(const float4*)(kr + (4 * n + quad) * 4);
                acc += qreg[4 * n + 0] * kv4.x + qreg[4 * n + 1] * kv4.y +
                       qreg[4 * n + 2] * kv4.z + qreg[4 * n + 3] * kv4.w;
            }
            acc += __shfl_xor_sync(0xffffffffu, acc, 1);
            acc += __shfl_xor_sync(0xffffffffu, acc, 2);
            const float p = (j < jmax) ? acc : -1e30f;
            mblk = fmaxf(mblk, p);
            if (quad == 0) Ps[row * 64 + j] = p;
        }
        __syncwarp();

        const float m_new = fmaxf(m_i, mblk);
        const float alpha = __expf(m_i - m_new);

        // pass B: exponentiate in place, accumulate row sum
        float lsum = 0.f;
        for (int j = 0; j < 64; j++) {
            const float e = __expf(Ps[row * 64 + j] - m_new);
            lsum += e;
            if (quad == 0) Ps[row * 64 + j] = e;
        }
        __syncwarp();

        m_i = m_new;
        l_i = l_i * alpha + lsum;
#pragma unroll
        for (int i = 0; i < 32; i++) oacc[i] *= alpha;

        // PV accumulate
        for (int j = 0; j < 64; j++) {
            const float e = Ps[row * 64 + j];
            const float* vr = Vs + j * 128;
#pragma unroll
            for (int n = 0; n < 8; n++) {
                float4 vv = *(const float4*)(vr + (4 * n + quad) * 4);
                oacc[4 * n + 0] += e * vv.x;
                oacc[4 * n + 1] += e * vv.y;
                oacc[4 * n + 2] += e * vv.z;
                oacc[4 * n + 3] += e * vv.w;
            }
        }
    }

    const float inv = 1.f / l_i;
    float* op = O + (((size_t)b * SEQ + qrow) * NH + h) * HD;
#pragma unroll
    for (int n = 0; n < 8; n++) {
        float4 v;
        v.x = oacc[4 * n + 0] * inv;
        v.y = oacc[4 * n + 1] * inv;
        v.z = oacc[4 * n + 2] * inv;
        v.w = oacc[4 * n + 3] * inv;
        *(float4*)(op + (4 * n + quad) * 4) = v;
    }
}

// ---------------------------------------------------------------------------
extern "C" void kernel_launch(void* const* d_in, const int* in_sizes, int n_in,
                              void* d_out, int out_size)
{
    const float* hs   = (const float*)d_in[0];
    const float* cosT = (const float*)d_in[1];
    const float* sinT = (const float*)d_in[2];
    // d_in[3] = attention_mask (exact causal; implemented analytically)
    const float* q_w = (const float*)d_in[4];
    const float* q_b = (const float*)d_in[5];
    const float* k_w = (const float*)d_in[6];
    const float* k_b = (const float*)d_in[7];
    const float* v_w = (const float*)d_in[8];
    const float* v_b = (const float*)d_in[9];
    const float* o_w = (const float*)d_in[10];
    float* out = (float*)d_out;

    float *Qb, *Kb, *Vb, *Ab;
    cudaGetSymbolAddress((void**)&Qb, g_Q);
    cudaGetSymbolAddress((void**)&Kb, g_K);
    cudaGetSymbolAddress((void**)&Vb, g_V);
    cudaGetSymbolAddress((void**)&Ab, g_A);

    // QKV projections
    sgemm_nt_kernel<<<dim3(HID / 128, M_ROWS / 128), 256>>>(hs, q_w, q_b, Qb, M_ROWS, HID, HID);
    sgemm_nt_kernel<<<dim3(KV_HID / 128, M_ROWS / 128), 256>>>(hs, k_w, k_b, Kb, M_ROWS, KV_HID, HID);
    sgemm_nt_kernel<<<dim3(KV_HID / 128, M_ROWS / 128), 256>>>(hs, v_w, v_b, Vb, M_ROWS, KV_HID, HID);

    // RoPE (in place on Q, K)
    rope_kernel<<<(BATCH * SEQ * 32 * 64) / 256, 256>>>(Qb, Kb, cosT, sinT);

    // Causal flash attention
    static const size_t smem_bytes = (2 * 64 * 128 + 64 * 64) * sizeof(float); // 80 KB
    cudaFuncSetAttribute(flash_kernel, cudaFuncAttributeMaxDynamicSharedMemorySize, (int)smem_bytes);
    flash_kernel<<<dim3(SEQ / 64, NH, BATCH), 256, smem_bytes>>>(Qb, Kb, Vb, Ab);

    // Output projection
    sgemm_nt_kernel<<<dim3(HID / 128, M_ROWS / 128), 256>>>(Ab, o_w, nullptr, out, M_ROWS, HID, HID);
}

// round 2
// speedup vs baseline: 1.6240x; 1.6240x over previous
#include <cuda_runtime.h>
#include <cuda_bf16.h>
#include <cstdint>

// Problem constants
#define BATCH 2
#define SEQ 2048
#define HID 3584
#define NH 28
#define NKV 4
#define HD 128
#define NREP 7
#define M_ROWS (BATCH * SEQ)           // 4096
#define KV_HID (NKV * HD)              // 512
#define SCALE_F 0.08838834764831845f   // 128^-0.5

// Scratch (device globals; allocation is forbidden)
__device__ float g_Q[(size_t)M_ROWS * HID];
__device__ float g_K[(size_t)M_ROWS * KV_HID];
__device__ float g_V[(size_t)M_ROWS * KV_HID];
__device__ float g_A[(size_t)M_ROWS * HID];

// ---------------------------------------------------------------------------
// TF32 tensor-core GEMM: C[M,N] = A[M,K] @ W[N,K]^T + bias
// 128x128 tile, BK=16, 256 threads (8 warps, warp tile 64x32), double-buffered.
// Fragments loaded with ldmatrix (f32 viewed as b16 pairs => exact tf32 frags).
// ---------------------------------------------------------------------------
#define LDA 20                 // padded smem row stride (floats): conflict-free ldmatrix
#define BUF_FLOATS (128 * LDA) // 2560 floats = 10240 bytes per buffer

__device__ __forceinline__ float to_tf32(float x) {
    asm("cvt.rna.tf32.f32 %0, %0;" : "+f"(x));
    return x;
}

__device__ __forceinline__ void ldmx4(uint32_t& r0, uint32_t& r1, uint32_t& r2,
                                      uint32_t& r3, uint32_t addr) {
    asm volatile("ldmatrix.sync.aligned.m8n8.x4.shared.b16 {%0,%1,%2,%3}, [%4];"
                 : "=r"(r0), "=r"(r1), "=r"(r2), "=r"(r3) : "r"(addr));
}

__device__ __forceinline__ void mma_tf32(float* c, const uint32_t* a,
                                         uint32_t b0, uint32_t b1) {
    asm volatile(
        "mma.sync.aligned.m16n8k8.row.col.f32.tf32.tf32.f32 "
        "{%0,%1,%2,%3}, {%4,%5,%6,%7}, {%8,%9}, {%0,%1,%2,%3};"
        : "+f"(c[0]), "+f"(c[1]), "+f"(c[2]), "+f"(c[3])
        : "r"(a[0]), "r"(a[1]), "r"(a[2]), "r"(a[3]), "r"(b0), "r"(b1));
}

__global__ void __launch_bounds__(256) tf32_gemm_nt(
    const float* __restrict__ A, const float* __restrict__ W,
    const float* __restrict__ bias, float* __restrict__ C,
    int M, int N, int K)
{
    __shared__ float As[2][BUF_FLOATS];
    __shared__ float Bs[2][BUF_FLOATS];

    const int bm = blockIdx.y * 128;
    const int bn = blockIdx.x * 128;
    const int tid = threadIdx.x;
    const int lane = tid & 31;
    const int wid = tid >> 5;
    const int wm = wid >> 2;   // 0..1  (64 rows per warp-m)
    const int wn = wid & 3;    // 0..3  (32 cols per warp-n)
    const int g = lane >> 3;   // ldmatrix address group
    const int lr = lane & 7;

    // smem base addresses (shared address space)
    const uint32_t sA = (uint32_t)__cvta_generic_to_shared(&As[0][0]);
    const uint32_t sB = (uint32_t)__cvta_generic_to_shared(&Bs[0][0]);

    // ldmatrix per-lane byte addresses (add buf offset + ks*4 in loop)
    uint32_t aBase[4], bBase[2];
#pragma unroll
    for (int m = 0; m < 4; m++) {
        int row = wm * 64 + m * 16 + lr + (g & 1) * 8;
        int col = (g >> 1) * 4;
        aBase[m] = sA + (row * LDA + col) * 4;
    }
#pragma unroll
    for (int p = 0; p < 2; p++) {
        int row = wn * 32 + p * 16 + lr + (g >> 1) * 8;
        int col = (g & 1) * 4;
        bBase[p] = sB + (row * LDA + col) * 4;
    }

    // gmem staging pointers: thread loads rows r and r+64 at col (tid&3)*4
    const int lrow = tid >> 2;
    const int lcol = (tid & 3) << 2;
    const float* Ap = A + (size_t)(bm + lrow) * K + lcol;
    const float* Wp = W + (size_t)(bn + lrow) * K + lcol;
    const int smoff = lrow * LDA + lcol;
    const int smoff2 = (lrow + 64) * LDA + lcol;

    float acc[4][4][4];
#pragma unroll
    for (int m = 0; m < 4; m++)
#pragma unroll
        for (int n = 0; n < 4; n++)
#pragma unroll
            for (int i = 0; i < 4; i++) acc[m][n][i] = 0.f;

    const int T = K / 16;

    // prologue: tile 0 -> buffer 0
    {
        float4 a0 = *(const float4*)(Ap);
        float4 a1 = *(const float4*)(Ap + (size_t)64 * K);
        float4 b0 = *(const float4*)(Wp);
        float4 b1 = *(const float4*)(Wp + (size_t)64 * K);
        As[0][smoff + 0] = to_tf32(a0.x); As[0][smoff + 1] = to_tf32(a0.y);
        As[0][smoff + 2] = to_tf32(a0.z); As[0][smoff + 3] = to_tf32(a0.w);
        As[0][smoff2 + 0] = to_tf32(a1.x); As[0][smoff2 + 1] = to_tf32(a1.y);
        As[0][smoff2 + 2] = to_tf32(a1.z); As[0][smoff2 + 3] = to_tf32(a1.w);
        Bs[0][smoff + 0] = to_tf32(b0.x); Bs[0][smoff + 1] = to_tf32(b0.y);
        Bs[0][smoff + 2] = to_tf32(b0.z); Bs[0][smoff + 3] = to_tf32(b0.w);
        Bs[0][smoff2 + 0] = to_tf32(b1.x); Bs[0][smoff2 + 1] = to_tf32(b1.y);
        Bs[0][smoff2 + 2] = to_tf32(b1.z); Bs[0][smoff2 + 3] = to_tf32(b1.w);
    }
    __syncthreads();

    for (int t = 0; t < T; t++) {
        const int cur = t & 1;
        const uint32_t bufoff = (uint32_t)cur * (BUF_FLOATS * 4);

        // issue gmem loads for next tile (overlap with compute)
        float4 a0, a1, b0, b1;
        if (t + 1 < T) {
            const int k0 = (t + 1) * 16;
            a0 = *(const float4*)(Ap + k0);
            a1 = *(const float4*)(Ap + (size_t)64 * K + k0);
            b0 = *(const float4*)(Wp + k0);
            b1 = *(const float4*)(Wp + (size_t)64 * K + k0);
        }

        // compute: 2 k8 steps from smem[cur]
#pragma unroll
        for (int ks = 0; ks < 16; ks += 8) {
            uint32_t afr[4][4];
#pragma unroll
            for (int m = 0; m < 4; m++)
                ldmx4(afr[m][0], afr[m][1], afr[m][2], afr[m][3],
                      aBase[m] + bufoff + ks * 4);
#pragma unroll
            for (int p = 0; p < 2; p++) {
                uint32_t bf0, bf1, bf2, bf3;
                ldmx4(bf0, bf1, bf2, bf3, bBase[p] + bufoff + ks * 4);
#pragma unroll
                for (int m = 0; m < 4; m++) {
                    mma_tf32(acc[m][2 * p + 0], afr[m], bf0, bf1);
                    mma_tf32(acc[m][2 * p + 1], afr[m], bf2, bf3);
                }
            }
        }

        // store staged tile into the other buffer
        if (t + 1 < T) {
            float* An = As[cur ^ 1];
            float* Bn = Bs[cur ^ 1];
            An[smoff + 0] = to_tf32(a0.x); An[smoff + 1] = to_tf32(a0.y);
            An[smoff + 2] = to_tf32(a0.z); An[smoff + 3] = to_tf32(a0.w);
            An[smoff2 + 0] = to_tf32(a1.x); An[smoff2 + 1] = to_tf32(a1.y);
            An[smoff2 + 2] = to_tf32(a1.z); An[smoff2 + 3] = to_tf32(a1.w);
            Bn[smoff + 0] = to_tf32(b0.x); Bn[smoff + 1] = to_tf32(b0.y);
            Bn[smoff + 2] = to_tf32(b0.z); Bn[smoff + 3] = to_tf32(b0.w);
            Bn[smoff2 + 0] = to_tf32(b1.x); Bn[smoff2 + 1] = to_tf32(b1.y);
            Bn[smoff2 + 2] = to_tf32(b1.z); Bn[smoff2 + 3] = to_tf32(b1.w);
        }
        __syncthreads();
    }

    // epilogue
#pragma unroll
    for (int m = 0; m < 4; m++) {
        const int row = bm + wm * 64 + m * 16 + (lane >> 2);
#pragma unroll
        for (int n = 0; n < 4; n++) {
            const int col = bn + wn * 32 + n * 8 + (lane & 3) * 2;
            float bx = 0.f, by = 0.f;
            if (bias) { bx = bias[col]; by = bias[col + 1]; }
            float2 v0 = make_float2(acc[m][n][0] + bx, acc[m][n][1] + by);
            float2 v1 = make_float2(acc[m][n][2] + bx, acc[m][n][3] + by);
            *(float2*)&C[(size_t)row * N + col] = v0;
            *(float2*)&C[(size_t)(row + 8) * N + col] = v1;
        }
    }
}

// ---------------------------------------------------------------------------
// RoPE in-place on Q and K.
// ---------------------------------------------------------------------------
__global__ void rope_kernel(float* __restrict__ Q, float* __restrict__ K,
                            const float* __restrict__ cosT,
                            const float* __restrict__ sinT)
{
    const int idx = blockIdx.x * blockDim.x + threadIdx.x;
    const int d = idx & 63;
    const int h = (idx >> 6) & 31;
    const int s = (idx >> 11) & 2047;
    const int b = idx >> 22;

    const float c1 = cosT[s * 128 + d];
    const float s1 = sinT[s * 128 + d];
    const float c2 = cosT[s * 128 + d + 64];
    const float s2 = sinT[s * 128 + d + 64];

    float* p;
    if (h < 28) p = Q + (((size_t)b * SEQ + s) * NH + h) * HD;
    else        p = K + (((size_t)b * SEQ + s) * NKV + (h - 28)) * HD;

    const float x1 = p[d];
    const float x2 = p[d + 64];
    p[d]      = x1 * c1 - x2 * s1;
    p[d + 64] = x2 * c2 + x1 * s2;
}

// ---------------------------------------------------------------------------
// Causal flash attention (fp32) — unchanged from R1.
// ---------------------------------------------------------------------------
__global__ void __launch_bounds__(256) flash_kernel(
    const float* __restrict__ Q, const float* __restrict__ K,
    const float* __restrict__ V, float* __restrict__ O)
{
    extern __shared__ float sm[];
    float* Ks = sm;
    float* Vs = sm + 64 * 128;
    float* Ps = sm + 2 * 64 * 128;

    const int qb = blockIdx.x, h = blockIdx.y, b = blockIdx.z;
    const int kvh = h / NREP;
    const int tid = threadIdx.x;
    const int row = tid >> 2;
    const int quad = tid & 3;
    const int qrow = qb * 64 + row;

    float qreg[32];
    {
        const float* qp = Q + (((size_t)b * SEQ + qrow) * NH + h) * HD;
#pragma unroll
        for (int n = 0; n < 8; n++) {
            float4 v = *(const float4*)(qp + (4 * n + quad) * 4);
            qreg[4 * n + 0] = v.x * SCALE_F;
            qreg[4 * n + 1] = v.y * SCALE_F;
            qreg[4 * n + 2] = v.z * SCALE_F;
            qreg[4 * n + 3] = v.w * SCALE_F;
        }
    }
    float oacc[32];
#pragma unroll
    for (int i = 0; i < 32; i++) oacc[i] = 0.f;
    float m_i = -1e30f, l_i = 0.f;

    const float* kbase = K + (((size_t)b * SEQ) * NKV + kvh) * HD;
    const float* vbase = V + (((size_t)b * SEQ) * NKV + kvh) * HD;

    for (int kb = 0; kb <= qb; kb++) {
        __syncthreads();
        {
            const float* kp = kbase + (size_t)kb * 64 * KV_HID;
            const float* vp = vbase + (size_t)kb * 64 * KV_HID;
#pragma unroll
            for (int it = 0; it < 8; it++) {
                const int idx = tid + it * 256;
                const int r = idx >> 5;
                const int c = (idx & 31) * 4;
                *(float4*)(Ks + r * 128 + c) = *(const float4*)(kp + (size_t)r * KV_HID + c);
                *(float4*)(Vs + r * 128 + c) = *(const float4*)(vp + (size_t)r * KV_HID + c);
            }
        }
        __syncthreads();

        const int jmax = (kb == qb) ? (row + 1) : 64;
        float mblk = -1e30f;

        for (int j = 0; j < 64; j++) {
            float acc = 0.f;
            const float* kr = Ks + j * 128;
#pragma unroll
            for (int n = 0; n < 8; n++) {
                float4 kv4 = *(const float4*)(kr + (4 * n + quad) * 4);
                acc += qreg[4 * n + 0] * kv4.x + qreg[4 * n + 1] * kv4.y +
                       qreg[4 * n + 2] * kv4.z + qreg[4 * n + 3] * kv4.w;
            }
            acc += __shfl_xor_sync(0xffffffffu, acc, 1);
            acc += __shfl_xor_sync(0xffffffffu, acc, 2);
            const float p = (j < jmax) ? acc : -1e30f;
            mblk = fmaxf(mblk, p);
            if (quad == 0) Ps[row * 64 + j] = p;
        }
        __syncwarp();

        const float m_new = fmaxf(m_i, mblk);
        const float alpha = __expf(m_i - m_new);

        float lsum = 0.f;
        for (int j = 0; j < 64; j++) {
            const float e = __expf(Ps[row * 64 + j] - m_new);
            lsum += e;
            if (quad == 0) Ps[row * 64 + j] = e;
        }
        __syncwarp();

        m_i = m_new;
        l_i = l_i * alpha + lsum;
#pragma unroll
        for (int i = 0; i < 32; i++) oacc[i] *= alpha;

        for (int j = 0; j < 64; j++) {
            const float e = Ps[row * 64 + j];
            const float* vr = Vs + j * 128;
#pragma unroll
            for (int n = 0; n < 8; n++) {
                float4 vv = *(const float4*)(vr + (4 * n + quad) * 4);
                oacc[4 * n + 0] += e * vv.x;
                oacc[4 * n + 1] += e * vv.y;
                oacc[4 * n + 2] += e * vv.z;
                oacc[4 * n + 3] += e * vv.w;
            }
        }
    }

    const float inv = 1.f / l_i;
    float* op = O + (((size_t)b * SEQ + qrow) * NH + h) * HD;
#pragma unroll
    for (int n = 0; n < 8; n++) {
        float4 v;
        v.x = oacc[4 * n + 0] * inv;
        v.y = oacc[4 * n + 1] * inv;
        v.z = oacc[4 * n + 2] * inv;
        v.w = oacc[4 * n + 3] * inv;
        *(float4*)(op + (4 * n + quad) * 4) = v;
    }
}

// ---------------------------------------------------------------------------
extern "C" void kernel_launch(void* const* d_in, const int* in_sizes, int n_in,
                              void* d_out, int out_size)
{
    const float* hs   = (const float*)d_in[0];
    const float* cosT = (const float*)d_in[1];
    const float* sinT = (const float*)d_in[2];
    const float* q_w = (const float*)d_in[4];
    const float* q_b = (const float*)d_in[5];
    const float* k_w = (const float*)d_in[6];
    const float* k_b = (const float*)d_in[7];
    const float* v_w = (const float*)d_in[8];
    const float* v_b = (const float*)d_in[9];
    const float* o_w = (const float*)d_in[10];
    float* out = (float*)d_out;

    float *Qb, *Kb, *Vb, *Ab;
    cudaGetSymbolAddress((void**)&Qb, g_Q);
    cudaGetSymbolAddress((void**)&Kb, g_K);
    cudaGetSymbolAddress((void**)&Vb, g_V);
    cudaGetSymbolAddress((void**)&Ab, g_A);

    // QKV projections (TF32 tensor cores)
    tf32_gemm_nt<<<dim3(HID / 128, M_ROWS / 128), 256>>>(hs, q_w, q_b, Qb, M_ROWS, HID, HID);
    tf32_gemm_nt<<<dim3(KV_HID / 128, M_ROWS / 128), 256>>>(hs, k_w, k_b, Kb, M_ROWS, KV_HID, HID);
    tf32_gemm_nt<<<dim3(KV_HID / 128, M_ROWS / 128), 256>>>(hs, v_w, v_b, Vb, M_ROWS, KV_HID, HID);

    // RoPE
    rope_kernel<<<(BATCH * SEQ * 32 * 64) / 256, 256>>>(Qb, Kb, cosT, sinT);

    // Causal flash attention
    static const size_t smem_bytes = (2 * 64 * 128 + 64 * 64) * sizeof(float);
    cudaFuncSetAttribute(flash_kernel, cudaFuncAttributeMaxDynamicSharedMemorySize, (int)smem_bytes);
    flash_kernel<<<dim3(SEQ / 64, NH, BATCH), 256, smem_bytes>>>(Qb, Kb, Vb, Ab);

    // Output projection (TF32 tensor cores)
    tf32_gemm_nt<<<dim3(HID / 128, M_ROWS / 128), 256>>>(Ab, o_w, nullptr, out, M_ROWS, HID, HID);
}

// round 3
// speedup vs baseline: 4.3927x; 2.7049x over previous
#include <cuda_runtime.h>
#include <cuda_bf16.h>
#include <cstdint>

// Problem constants
#define BATCH 2
#define SEQ 2048
#define HID 3584
#define NH 28
#define NKV 4
#define HD 128
#define NREP 7
#define M_ROWS (BATCH * SEQ)           // 4096
#define KV_HID (NKV * HD)              // 512
#define SCALE_F 0.08838834764831845f   // 128^-0.5

// Scratch (device globals; allocation is forbidden)
__device__ float g_Q[(size_t)M_ROWS * HID];
__device__ float g_K[(size_t)M_ROWS * KV_HID];
__device__ float g_V[(size_t)M_ROWS * KV_HID];
__device__ float g_A[(size_t)M_ROWS * HID];

// ---------------------------------------------------------------------------
// Common helpers
// ---------------------------------------------------------------------------
__device__ __forceinline__ float to_tf32(float x) {
    asm("cvt.rna.tf32.f32 %0, %0;" : "+f"(x));
    return x;
}
__device__ __forceinline__ uint32_t rna_u(uint32_t x) {
    float f = __uint_as_float(x);
    asm("cvt.rna.tf32.f32 %0, %0;" : "+f"(f));
    return __float_as_uint(f);
}
__device__ __forceinline__ void ldmx4(uint32_t& r0, uint32_t& r1, uint32_t& r2,
                                      uint32_t& r3, uint32_t addr) {
    asm volatile("ldmatrix.sync.aligned.m8n8.x4.shared.b16 {%0,%1,%2,%3}, [%4];"
                 : "=r"(r0), "=r"(r1), "=r"(r2), "=r"(r3) : "r"(addr));
}
__device__ __forceinline__ void mma_tf32(float* c, const uint32_t* a,
                                         uint32_t b0, uint32_t b1) {
    asm volatile(
        "mma.sync.aligned.m16n8k8.row.col.f32.tf32.tf32.f32 "
        "{%0,%1,%2,%3}, {%4,%5,%6,%7}, {%8,%9}, {%0,%1,%2,%3};"
        : "+f"(c[0]), "+f"(c[1]), "+f"(c[2]), "+f"(c[3])
        : "r"(a[0]), "r"(a[1]), "r"(a[2]), "r"(a[3]), "r"(b0), "r"(b1));
}
__device__ __forceinline__ void mma_tf32f(float* c, const float* a,
                                          float b0f, float b1f) {
    uint32_t a0 = __float_as_uint(a[0]), a1 = __float_as_uint(a[1]);
    uint32_t a2 = __float_as_uint(a[2]), a3 = __float_as_uint(a[3]);
    uint32_t b0 = __float_as_uint(b0f), b1 = __float_as_uint(b1f);
    asm volatile(
        "mma.sync.aligned.m16n8k8.row.col.f32.tf32.tf32.f32 "
        "{%0,%1,%2,%3}, {%4,%5,%6,%7}, {%8,%9}, {%0,%1,%2,%3};"
        : "+f"(c[0]), "+f"(c[1]), "+f"(c[2]), "+f"(c[3])
        : "r"(a0), "r"(a1), "r"(a2), "r"(a3), "r"(b0), "r"(b1));
}
__device__ __forceinline__ void cp16(uint32_t dst, const void* src) {
    asm volatile("cp.async.cg.shared.global [%0], [%1], 16;" :: "r"(dst), "l"(src));
}
__device__ __forceinline__ void cp_commit() {
    asm volatile("cp.async.commit_group;");
}
template <int N>
__device__ __forceinline__ void cp_wait() {
    asm volatile("cp.async.wait_group %0;" :: "n"(N));
}

// ---------------------------------------------------------------------------
// TF32 tensor-core GEMM: C[M,N] = A[M,K] @ W[N,K]^T + bias
// 128x128 tile, BK=16, 256 threads, 3-stage cp.async pipeline.
// smem holds raw fp32; fragments rounded to tf32 (rna) after ldmatrix.
// ---------------------------------------------------------------------------
#define LDA 20                 // padded smem row stride (floats)
#define BUF_FLOATS (128 * LDA)
#define BUF_BYTES (BUF_FLOATS * 4)

__global__ void __launch_bounds__(256) tf32_gemm_nt(
    const float* __restrict__ A, const float* __restrict__ W,
    const float* __restrict__ bias, float* __restrict__ C,
    int M, int N, int K)
{
    __shared__ __align__(16) float As[3][BUF_FLOATS];
    __shared__ __align__(16) float Bs[3][BUF_FLOATS];

    const int bm = blockIdx.y * 128;
    const int bn = blockIdx.x * 128;
    const int tid = threadIdx.x;
    const int lane = tid & 31;
    const int wid = tid >> 5;
    const int wm = wid >> 2;
    const int wn = wid & 3;
    const int g = lane >> 3;
    const int lr = lane & 7;

    const uint32_t sA = (uint32_t)__cvta_generic_to_shared(&As[0][0]);
    const uint32_t sB = (uint32_t)__cvta_generic_to_shared(&Bs[0][0]);

    uint32_t aBase[4], bBase[2];
#pragma unroll
    for (int m = 0; m < 4; m++) {
        int row = wm * 64 + m * 16 + lr + (g & 1) * 8;
        int col = (g >> 1) * 4;
        aBase[m] = sA + (row * LDA + col) * 4;
    }
#pragma unroll
    for (int p = 0; p < 2; p++) {
        int row = wn * 32 + p * 16 + lr + (g >> 1) * 8;
        int col = (g & 1) * 4;
        bBase[p] = sB + (row * LDA + col) * 4;
    }

    const int lrow = tid >> 2;
    const int lcol = (tid & 3) << 2;
    const float* Ap = A + (size_t)(bm + lrow) * K + lcol;
    const float* Wp = W + (size_t)(bn + lrow) * K + lcol;
    const uint32_t smoff = (lrow * LDA + lcol) * 4;
    const uint32_t smoff2 = smoff + 64 * LDA * 4;

    auto issue = [&](int t, int s) {
        const uint32_t da = sA + (uint32_t)s * BUF_BYTES;
        const uint32_t db = sB + (uint32_t)s * BUF_BYTES;
        const float* ap = Ap + t * 16;
        const float* wp = Wp + t * 16;
        cp16(da + smoff, ap);
        cp16(da + smoff2, ap + (size_t)64 * K);
        cp16(db + smoff, wp);
        cp16(db + smoff2, wp + (size_t)64 * K);
        cp_commit();
    };

    float acc[4][4][4];
#pragma unroll
    for (int m = 0; m < 4; m++)
#pragma unroll
        for (int n = 0; n < 4; n++)
#pragma unroll
            for (int i = 0; i < 4; i++) acc[m][n][i] = 0.f;

    const int T = K / 16;
    issue(0, 0);
    issue(1, 1);

    for (int t = 0; t < T; t++) {
        if (t + 1 < T) cp_wait<1>(); else cp_wait<0>();
        __syncthreads();
        if (t + 2 < T) issue(t + 2, (t + 2) % 3);

        const uint32_t bufoff = (uint32_t)(t % 3) * BUF_BYTES;
#pragma unroll
        for (int ks = 0; ks < 16; ks += 8) {
            uint32_t afr[4][4];
#pragma unroll
            for (int m = 0; m < 4; m++) {
                ldmx4(afr[m][0], afr[m][1], afr[m][2], afr[m][3],
                      aBase[m] + bufoff + ks * 4);
                afr[m][0] = rna_u(afr[m][0]); afr[m][1] = rna_u(afr[m][1]);
                afr[m][2] = rna_u(afr[m][2]); afr[m][3] = rna_u(afr[m][3]);
            }
#pragma unroll
            for (int p = 0; p < 2; p++) {
                uint32_t bf0, bf1, bf2, bf3;
                ldmx4(bf0, bf1, bf2, bf3, bBase[p] + bufoff + ks * 4);
                bf0 = rna_u(bf0); bf1 = rna_u(bf1);
                bf2 = rna_u(bf2); bf3 = rna_u(bf3);
#pragma unroll
                for (int m = 0; m < 4; m++) {
                    mma_tf32(acc[m][2 * p + 0], afr[m], bf0, bf1);
                    mma_tf32(acc[m][2 * p + 1], afr[m], bf2, bf3);
                }
            }
        }
    }

#pragma unroll
    for (int m = 0; m < 4; m++) {
        const int row = bm + wm * 64 + m * 16 + (lane >> 2);
#pragma unroll
        for (int n = 0; n < 4; n++) {
            const int col = bn + wn * 32 + n * 8 + (lane & 3) * 2;
            float bx = 0.f, by = 0.f;
            if (bias) { bx = bias[col]; by = bias[col + 1]; }
            float2 v0 = make_float2(acc[m][n][0] + bx, acc[m][n][1] + by);
            float2 v1 = make_float2(acc[m][n][2] + bx, acc[m][n][3] + by);
            *(float2*)&C[(size_t)row * N + col] = v0;
            *(float2*)&C[(size_t)(row + 8) * N + col] = v1;
        }
    }
}

// ---------------------------------------------------------------------------
// RoPE in-place on Q and K.
// ---------------------------------------------------------------------------
__global__ void rope_kernel(float* __restrict__ Q, float* __restrict__ K,
                            const float* __restrict__ cosT,
                            const float* __restrict__ sinT)
{
    const int idx = blockIdx.x * blockDim.x + threadIdx.x;
    const int d = idx & 63;
    const int h = (idx >> 6) & 31;
    const int s = (idx >> 11) & 2047;
    const int b = idx >> 22;

    const float c1 = cosT[s * 128 + d];
    const float s1 = sinT[s * 128 + d];
    const float c2 = cosT[s * 128 + d + 64];
    const float s2 = sinT[s * 128 + d + 64];

    float* p;
    if (h < 28) p = Q + (((size_t)b * SEQ + s) * NH + h) * HD;
    else        p = K + (((size_t)b * SEQ + s) * NKV + (h - 28)) * HD;

    const float x1 = p[d];
    const float x2 = p[d + 64];
    p[d]      = x1 * c1 - x2 * s1;
    p[d + 64] = x2 * c2 + x1 * s2;
}

// ---------------------------------------------------------------------------
// Tensor-core causal flash attention.
// Q block 128 rows (8 warps x m16), KV block 64.
// QK^T: 3xTF32 (hi/lo split) => fp32-grade scores. PV: plain tf32 (rna).
// smem strides: Q/K 132 (bank-free for 4r+q patterns), V 136 (for 8q+r).
// ---------------------------------------------------------------------------
#define QB 128
#define KB 64
#define LDK 132
#define LDV 136

__global__ void __launch_bounds__(256, 1) flash_tc(
    const float* __restrict__ Q, const float* __restrict__ K,
    const float* __restrict__ V, float* __restrict__ O)
{
    extern __shared__ float sm[];
    float* Qs  = sm;                         // 128*132
    float* Khi = Qs + QB * LDK;              // 64*132
    float* Klo = Khi + KB * LDK;             // 64*132
    float* Vs  = Klo + KB * LDK;             // 64*136

    const int qb = blockIdx.x, h = blockIdx.y, b = blockIdx.z;
    const int kvh = h / NREP;
    const int tid = threadIdx.x;
    const int lane = tid & 31;
    const int w = tid >> 5;
    const int q4 = lane & 3;
    const int r4 = lane >> 2;

    // Load + scale Q block into smem
#pragma unroll
    for (int j = 0; j < 16; j++) {
        const int fid = tid + j * 256;        // 0..4095 float4s
        const int row = fid >> 5;
        const int c4 = (fid & 31) << 2;
        float4 v = *(const float4*)(Q + (((size_t)b * SEQ + qb * QB + row) * NH + h) * HD + c4);
        float* d = Qs + row * LDK + c4;
        d[0] = v.x * SCALE_F; d[1] = v.y * SCALE_F;
        d[2] = v.z * SCALE_F; d[3] = v.w * SCALE_F;
    }

    float oacc[16][4];
#pragma unroll
    for (int i = 0; i < 16; i++)
#pragma unroll
        for (int c = 0; c < 4; c++) oacc[i][c] = 0.f;
    float m0 = -1e30f, m1 = -1e30f, l0 = 0.f, l1 = 0.f;

    const int row0 = w * 16 + r4;             // local q row
    const int rg0 = qb * QB + row0;
    const int rg1 = rg0 + 8;

    const float* Kb_ = K + ((size_t)b * SEQ * NKV + kvh) * HD;
    const float* Vb_ = V + ((size_t)b * SEQ * NKV + kvh) * HD;

    const int kbmax = 2 * qb + 1;
    for (int kb = 0; kb <= kbmax; kb++) {
        __syncthreads();
        // Load K (split hi/lo) and V (pre-rounded tf32)
#pragma unroll
        for (int j = 0; j < 8; j++) {
            const int fid = tid + j * 256;    // 0..2047 float4s
            const int row = fid >> 5;
            const int c4 = (fid & 31) << 2;
            const size_t goff = (size_t)(kb * KB + row) * KV_HID + c4;
            float4 kv = *(const float4*)(Kb_ + goff);
            float4 vv = *(const float4*)(Vb_ + goff);
            float* kh = Khi + row * LDK + c4;
            float* kl = Klo + row * LDK + c4;
            float hx = to_tf32(kv.x), hy = to_tf32(kv.y),
                  hz = to_tf32(kv.z), hw = to_tf32(kv.w);
            kh[0] = hx; kh[1] = hy; kh[2] = hz; kh[3] = hw;
            kl[0] = to_tf32(kv.x - hx); kl[1] = to_tf32(kv.y - hy);
            kl[2] = to_tf32(kv.z - hz); kl[3] = to_tf32(kv.w - hw);
            float* vp = Vs + row * LDV + c4;
            vp[0] = to_tf32(vv.x); vp[1] = to_tf32(vv.y);
            vp[2] = to_tf32(vv.z); vp[3] = to_tf32(vv.w);
        }
        __syncthreads();

        // ---- S = Q Kᵀ (3xTF32) ----
        float sacc[8][4];
#pragma unroll
        for (int nt = 0; nt < 8; nt++)
#pragma unroll
            for (int c = 0; c < 4; c++) sacc[nt][c] = 0.f;

#pragma unroll 4
        for (int kt = 0; kt < 16; kt++) {
            const float* qp = Qs + row0 * LDK + kt * 8 + q4;
            const float f0 = qp[0], f1 = qp[8 * LDK], f2 = qp[4], f3 = qp[8 * LDK + 4];
            float ah[4], al[4];
            ah[0] = to_tf32(f0); ah[1] = to_tf32(f1);
            ah[2] = to_tf32(f2); ah[3] = to_tf32(f3);
            al[0] = to_tf32(f0 - ah[0]); al[1] = to_tf32(f1 - ah[1]);
            al[2] = to_tf32(f2 - ah[2]); al[3] = to_tf32(f3 - ah[3]);
#pragma unroll
            for (int nt = 0; nt < 8; nt++) {
                const int ko = (nt * 8 + r4) * LDK + kt * 8 + q4;
                const float bh0 = Khi[ko], bh1 = Khi[ko + 4];
                const float bl0 = Klo[ko], bl1 = Klo[ko + 4];
                mma_tf32f(sacc[nt], ah, bh0, bh1);
                mma_tf32f(sacc[nt], al, bh0, bh1);
                mma_tf32f(sacc[nt], ah, bl0, bl1);
            }
        }

        // ---- mask + online softmax ----
        if (kb >= 2 * qb) {
            const int colb = kb * KB + 2 * q4;
#pragma unroll
            for (int nt = 0; nt < 8; nt++) {
                const int c0 = colb + nt * 8;
                if (c0 > rg0)     sacc[nt][0] = -1e30f;
                if (c0 + 1 > rg0) sacc[nt][1] = -1e30f;
                if (c0 > rg1)     sacc[nt][2] = -1e30f;
                if (c0 + 1 > rg1) sacc[nt][3] = -1e30f;
            }
        }
        float mb0 = -1e30f, mb1 = -1e30f;
#pragma unroll
        for (int nt = 0; nt < 8; nt++) {
            mb0 = fmaxf(mb0, fmaxf(sacc[nt][0], sacc[nt][1]));
            mb1 = fmaxf(mb1, fmaxf(sacc[nt][2], sacc[nt][3]));
        }
        mb0 = fmaxf(mb0, __shfl_xor_sync(0xffffffffu, mb0, 1));
        mb0 = fmaxf(mb0, __shfl_xor_sync(0xffffffffu, mb0, 2));
        mb1 = fmaxf(mb1, __shfl_xor_sync(0xffffffffu, mb1, 1));
        mb1 = fmaxf(mb1, __shfl_xor_sync(0xffffffffu, mb1, 2));

        const float mn0 = fmaxf(m0, mb0), mn1 = fmaxf(m1, mb1);
        const float a0 = __expf(m0 - mn0), a1 = __expf(m1 - mn1);
        m0 = mn0; m1 = mn1;

        float ls0 = 0.f, ls1 = 0.f;
#pragma unroll
        for (int nt = 0; nt < 8; nt++) {
            float p0 = to_tf32(__expf(sacc[nt][0] - mn0));
            float p1 = to_tf32(__expf(sacc[nt][1] - mn0));
            float p2 = to_tf32(__expf(sacc[nt][2] - mn1));
            float p3 = to_tf32(__expf(sacc[nt][3] - mn1));
            sacc[nt][0] = p0; sacc[nt][1] = p1;
            sacc[nt][2] = p2; sacc[nt][3] = p3;
            ls0 += p0 + p1; ls1 += p2 + p3;
        }
        ls0 += __shfl_xor_sync(0xffffffffu, ls0, 1);
        ls0 += __shfl_xor_sync(0xffffffffu, ls0, 2);
        ls1 += __shfl_xor_sync(0xffffffffu, ls1, 1);
        ls1 += __shfl_xor_sync(0xffffffffu, ls1, 2);
        l0 = l0 * a0 + ls0;
        l1 = l1 * a1 + ls1;

#pragma unroll
        for (int nt2 = 0; nt2 < 16; nt2++) {
            oacc[nt2][0] *= a0; oacc[nt2][1] *= a0;
            oacc[nt2][2] *= a1; oacc[nt2][3] *= a1;
        }

        // ---- O += P V (plain tf32) ----
        const int src0 = (lane & ~3) | (q4 >> 1);
        const int src1 = src0 | 2;
        const bool oddq = (q4 & 1);
#pragma unroll
        for (int kt2 = 0; kt2 < 8; kt2++) {
            const float t00 = __shfl_sync(0xffffffffu, sacc[kt2][0], src0);
            const float t01 = __shfl_sync(0xffffffffu, sacc[kt2][1], src0);
            const float t02 = __shfl_sync(0xffffffffu, sacc[kt2][2], src0);
            const float t03 = __shfl_sync(0xffffffffu, sacc[kt2][3], src0);
            const float t10 = __shfl_sync(0xffffffffu, sacc[kt2][0], src1);
            const float t11 = __shfl_sync(0xffffffffu, sacc[kt2][1], src1);
            const float t12 = __shfl_sync(0xffffffffu, sacc[kt2][2], src1);
            const float t13 = __shfl_sync(0xffffffffu, sacc[kt2][3], src1);
            float pa[4];
            pa[0] = oddq ? t01 : t00;
            pa[1] = oddq ? t03 : t02;
            pa[2] = oddq ? t11 : t10;
            pa[3] = oddq ? t13 : t12;
            const float* vrow = Vs + (kt2 * 8 + q4) * LDV + r4;
#pragma unroll
            for (int nt2 = 0; nt2 < 16; nt2++) {
                mma_tf32f(oacc[nt2], pa, vrow[nt2 * 8], vrow[nt2 * 8 + 4 * LDV]);
            }
        }
    }

    // epilogue
    const float inv0 = 1.f / l0, inv1 = 1.f / l1;
    float* o0 = O + (((size_t)b * SEQ + rg0) * NH + h) * HD;
    float* o1 = O + (((size_t)b * SEQ + rg1) * NH + h) * HD;
#pragma unroll
    for (int nt2 = 0; nt2 < 16; nt2++) {
        const int col = nt2 * 8 + 2 * q4;
        *(float2*)(o0 + col) = make_float2(oacc[nt2][0] * inv0, oacc[nt2][1] * inv0);
        *(float2*)(o1 + col) = make_float2(oacc[nt2][2] * inv1, oacc[nt2][3] * inv1);
    }
}

// ---------------------------------------------------------------------------
extern "C" void kernel_launch(void* const* d_in, const int* in_sizes, int n_in,
                              void* d_out, int out_size)
{
    const float* hs   = (const float*)d_in[0];
    const float* cosT = (const float*)d_in[1];
    const float* sinT = (const float*)d_in[2];
    const float* q_w = (const float*)d_in[4];
    const float* q_b = (const float*)d_in[5];
    const float* k_w = (const float*)d_in[6];
    const float* k_b = (const float*)d_in[7];
    const float* v_w = (const float*)d_in[8];
    const float* v_b = (const float*)d_in[9];
    const float* o_w = (const float*)d_in[10];
    float* out = (float*)d_out;

    float *Qb, *Kb, *Vb, *Ab;
    cudaGetSymbolAddress((void**)&Qb, g_Q);
    cudaGetSymbolAddress((void**)&Kb, g_K);
    cudaGetSymbolAddress((void**)&Vb, g_V);
    cudaGetSymbolAddress((void**)&Ab, g_A);

    // QKV projections (TF32 tensor cores, cp.async pipelined)
    tf32_gemm_nt<<<dim3(HID / 128, M_ROWS / 128), 256>>>(hs, q_w, q_b, Qb, M_ROWS, HID, HID);
    tf32_gemm_nt<<<dim3(KV_HID / 128, M_ROWS / 128), 256>>>(hs, k_w, k_b, Kb, M_ROWS, KV_HID, HID);
    tf32_gemm_nt<<<dim3(KV_HID / 128, M_ROWS / 128), 256>>>(hs, v_w, v_b, Vb, M_ROWS, KV_HID, HID);

    // RoPE
    rope_kernel<<<(BATCH * SEQ * 32 * 64) / 256, 256>>>(Qb, Kb, cosT, sinT);

    // Tensor-core causal flash attention
    static const int flash_smem = (QB * LDK + 2 * KB * LDK + KB * LDV) * 4; // 169,984 B
    cudaFuncSetAttribute(flash_tc, cudaFuncAttributeMaxDynamicSharedMemorySize, flash_smem);
    flash_tc<<<dim3(SEQ / QB, NH, BATCH), 256, flash_smem>>>(Qb, Kb, Vb, Ab);

    // Output projection
    tf32_gemm_nt<<<dim3(HID / 128, M_ROWS / 128), 256>>>(Ab, o_w, nullptr, out, M_ROWS, HID, HID);
}

// round 4
// speedup vs baseline: 5.2396x; 1.1928x over previous
#include <cuda_runtime.h>
#include <cuda_bf16.h>
#include <cstdint>

// Problem constants
#define BATCH 2
#define SEQ 2048
#define HID 3584
#define NH 28
#define NKV 4
#define HD 128
#define NREP 7
#define M_ROWS (BATCH * SEQ)           // 4096
#define KV_HID (NKV * HD)              // 512
#define SCALE_F 0.08838834764831845f   // 128^-0.5

// Scratch (device globals; allocation is forbidden)
__device__ float g_Q[(size_t)M_ROWS * HID];
__device__ float g_K[(size_t)M_ROWS * KV_HID];
__device__ float g_V[(size_t)M_ROWS * KV_HID];
__device__ float g_A[(size_t)M_ROWS * HID];
__device__ __nv_bfloat16 g_Qhi[(size_t)M_ROWS * HID];
__device__ __nv_bfloat16 g_Qlo[(size_t)M_ROWS * HID];
__device__ __nv_bfloat16 g_Khi[(size_t)M_ROWS * KV_HID];
__device__ __nv_bfloat16 g_Klo[(size_t)M_ROWS * KV_HID];

// ---------------------------------------------------------------------------
// Common helpers
// ---------------------------------------------------------------------------
__device__ __forceinline__ float to_tf32(float x) {
    asm("cvt.rna.tf32.f32 %0, %0;" : "+f"(x));
    return x;
}
__device__ __forceinline__ uint32_t rna_u(uint32_t x) {
    float f = __uint_as_float(x);
    asm("cvt.rna.tf32.f32 %0, %0;" : "+f"(f));
    return __float_as_uint(f);
}
__device__ __forceinline__ void ldmx4(uint32_t& r0, uint32_t& r1, uint32_t& r2,
                                      uint32_t& r3, uint32_t addr) {
    asm volatile("ldmatrix.sync.aligned.m8n8.x4.shared.b16 {%0,%1,%2,%3}, [%4];"
                 : "=r"(r0), "=r"(r1), "=r"(r2), "=r"(r3) : "r"(addr));
}
__device__ __forceinline__ void mma_tf32(float* c, const uint32_t* a,
                                         uint32_t b0, uint32_t b1) {
    asm volatile(
        "mma.sync.aligned.m16n8k8.row.col.f32.tf32.tf32.f32 "
        "{%0,%1,%2,%3}, {%4,%5,%6,%7}, {%8,%9}, {%0,%1,%2,%3};"
        : "+f"(c[0]), "+f"(c[1]), "+f"(c[2]), "+f"(c[3])
        : "r"(a[0]), "r"(a[1]), "r"(a[2]), "r"(a[3]), "r"(b0), "r"(b1));
}
__device__ __forceinline__ void mma_tf32f(float* c, const float* a,
                                          float b0f, float b1f) {
    uint32_t a0 = __float_as_uint(a[0]), a1 = __float_as_uint(a[1]);
    uint32_t a2 = __float_as_uint(a[2]), a3 = __float_as_uint(a[3]);
    uint32_t b0 = __float_as_uint(b0f), b1 = __float_as_uint(b1f);
    asm volatile(
        "mma.sync.aligned.m16n8k8.row.col.f32.tf32.tf32.f32 "
        "{%0,%1,%2,%3}, {%4,%5,%6,%7}, {%8,%9}, {%0,%1,%2,%3};"
        : "+f"(c[0]), "+f"(c[1]), "+f"(c[2]), "+f"(c[3])
        : "r"(a0), "r"(a1), "r"(a2), "r"(a3), "r"(b0), "r"(b1));
}
__device__ __forceinline__ void mma_bf16(float* c, const uint32_t* a,
                                         uint32_t b0, uint32_t b1) {
    asm volatile(
        "mma.sync.aligned.m16n8k16.row.col.f32.bf16.bf16.f32 "
        "{%0,%1,%2,%3}, {%4,%5,%6,%7}, {%8,%9}, {%0,%1,%2,%3};"
        : "+f"(c[0]), "+f"(c[1]), "+f"(c[2]), "+f"(c[3])
        : "r"(a[0]), "r"(a[1]), "r"(a[2]), "r"(a[3]), "r"(b0), "r"(b1));
}
__device__ __forceinline__ void cp16(uint32_t dst, const void* src) {
    asm volatile("cp.async.cg.shared.global [%0], [%1], 16;" :: "r"(dst), "l"(src));
}
__device__ __forceinline__ void cp_commit() {
    asm volatile("cp.async.commit_group;");
}
template <int N>
__device__ __forceinline__ void cp_wait() {
    asm volatile("cp.async.wait_group %0;" :: "n"(N));
}
__device__ __forceinline__ void bsplit(float x, __nv_bfloat16& hi, __nv_bfloat16& lo) {
    hi = __float2bfloat16(x);
    lo = __float2bfloat16(x - __bfloat162float(hi));
}

// ---------------------------------------------------------------------------
// TF32 tensor-core GEMM: C[M,N] = A[M,K] @ W[N,K]^T + bias
// 128x128 tile, BK=16, 256 threads, 3-stage cp.async pipeline. (as R3)
// rnd!=0: round outputs to tf32 (rna) in epilogue (used for V).
// ---------------------------------------------------------------------------
#define LDA 20
#define BUF_FLOATS (128 * LDA)
#define BUF_BYTES (BUF_FLOATS * 4)

__global__ void __launch_bounds__(256) tf32_gemm_nt(
    const float* __restrict__ A, const float* __restrict__ W,
    const float* __restrict__ bias, float* __restrict__ C,
    int M, int N, int K, int rnd)
{
    __shared__ __align__(16) float As[3][BUF_FLOATS];
    __shared__ __align__(16) float Bs[3][BUF_FLOATS];

    const int bm = blockIdx.y * 128;
    const int bn = blockIdx.x * 128;
    const int tid = threadIdx.x;
    const int lane = tid & 31;
    const int wid = tid >> 5;
    const int wm = wid >> 2;
    const int wn = wid & 3;
    const int g = lane >> 3;
    const int lr = lane & 7;

    const uint32_t sA = (uint32_t)__cvta_generic_to_shared(&As[0][0]);
    const uint32_t sB = (uint32_t)__cvta_generic_to_shared(&Bs[0][0]);

    uint32_t aBase[4], bBase[2];
#pragma unroll
    for (int m = 0; m < 4; m++) {
        int row = wm * 64 + m * 16 + lr + (g & 1) * 8;
        int col = (g >> 1) * 4;
        aBase[m] = sA + (row * LDA + col) * 4;
    }
#pragma unroll
    for (int p = 0; p < 2; p++) {
        int row = wn * 32 + p * 16 + lr + (g >> 1) * 8;
        int col = (g & 1) * 4;
        bBase[p] = sB + (row * LDA + col) * 4;
    }

    const int lrow = tid >> 2;
    const int lcol = (tid & 3) << 2;
    const float* Ap = A + (size_t)(bm + lrow) * K + lcol;
    const float* Wp = W + (size_t)(bn + lrow) * K + lcol;
    const uint32_t smoff = (lrow * LDA + lcol) * 4;
    const uint32_t smoff2 = smoff + 64 * LDA * 4;

    auto issue = [&](int t, int s) {
        const uint32_t da = sA + (uint32_t)s * BUF_BYTES;
        const uint32_t db = sB + (uint32_t)s * BUF_BYTES;
        const float* ap = Ap + t * 16;
        const float* wp = Wp + t * 16;
        cp16(da + smoff, ap);
        cp16(da + smoff2, ap + (size_t)64 * K);
        cp16(db + smoff, wp);
        cp16(db + smoff2, wp + (size_t)64 * K);
        cp_commit();
    };

    float acc[4][4][4];
#pragma unroll
    for (int m = 0; m < 4; m++)
#pragma unroll
        for (int n = 0; n < 4; n++)
#pragma unroll
            for (int i = 0; i < 4; i++) acc[m][n][i] = 0.f;

    const int T = K / 16;
    issue(0, 0);
    issue(1, 1);

    for (int t = 0; t < T; t++) {
        if (t + 1 < T) cp_wait<1>(); else cp_wait<0>();
        __syncthreads();
        if (t + 2 < T) issue(t + 2, (t + 2) % 3);

        const uint32_t bufoff = (uint32_t)(t % 3) * BUF_BYTES;
#pragma unroll
        for (int ks = 0; ks < 16; ks += 8) {
            uint32_t afr[4][4];
#pragma unroll
            for (int m = 0; m < 4; m++) {
                ldmx4(afr[m][0], afr[m][1], afr[m][2], afr[m][3],
                      aBase[m] + bufoff + ks * 4);
                afr[m][0] = rna_u(afr[m][0]); afr[m][1] = rna_u(afr[m][1]);
                afr[m][2] = rna_u(afr[m][2]); afr[m][3] = rna_u(afr[m][3]);
            }
#pragma unroll
            for (int p = 0; p < 2; p++) {
                uint32_t bf0, bf1, bf2, bf3;
                ldmx4(bf0, bf1, bf2, bf3, bBase[p] + bufoff + ks * 4);
                bf0 = rna_u(bf0); bf1 = rna_u(bf1);
                bf2 = rna_u(bf2); bf3 = rna_u(bf3);
#pragma unroll
                for (int m = 0; m < 4; m++) {
                    mma_tf32(acc[m][2 * p + 0], afr[m], bf0, bf1);
                    mma_tf32(acc[m][2 * p + 1], afr[m], bf2, bf3);
                }
            }
        }
    }

#pragma unroll
    for (int m = 0; m < 4; m++) {
        const int row = bm + wm * 64 + m * 16 + (lane >> 2);
#pragma unroll
        for (int n = 0; n < 4; n++) {
            const int col = bn + wn * 32 + n * 8 + (lane & 3) * 2;
            float bx = 0.f, by = 0.f;
            if (bias) { bx = bias[col]; by = bias[col + 1]; }
            float2 v0 = make_float2(acc[m][n][0] + bx, acc[m][n][1] + by);
            float2 v1 = make_float2(acc[m][n][2] + bx, acc[m][n][3] + by);
            if (rnd) {
                v0.x = to_tf32(v0.x); v0.y = to_tf32(v0.y);
                v1.x = to_tf32(v1.x); v1.y = to_tf32(v1.y);
            }
            *(float2*)&C[(size_t)row * N + col] = v0;
            *(float2*)&C[(size_t)(row + 8) * N + col] = v1;
        }
    }
}

// ---------------------------------------------------------------------------
// RoPE + bf16 hi/lo split. Q additionally prescaled by SCALE_F.
// Writes split arrays consumed by the flash kernel.
// ---------------------------------------------------------------------------
__global__ void rope_split(const float* __restrict__ Q, const float* __restrict__ K,
                           const float* __restrict__ cosT, const float* __restrict__ sinT,
                           __nv_bfloat16* __restrict__ Qh, __nv_bfloat16* __restrict__ Ql,
                           __nv_bfloat16* __restrict__ Kh, __nv_bfloat16* __restrict__ Kl)
{
    const int idx = blockIdx.x * blockDim.x + threadIdx.x;
    const int d = idx & 63;
    const int h = (idx >> 6) & 31;
    const int s = (idx >> 11) & 2047;
    const int b = idx >> 22;

    const float c1 = cosT[s * 128 + d];
    const float s1 = sinT[s * 128 + d];
    const float c2 = cosT[s * 128 + d + 64];
    const float s2 = sinT[s * 128 + d + 64];

    if (h < 28) {
        const size_t base = (((size_t)b * SEQ + s) * NH + h) * HD;
        const float x1 = Q[base + d];
        const float x2 = Q[base + d + 64];
        const float r1 = (x1 * c1 - x2 * s1) * SCALE_F;
        const float r2 = (x2 * c2 + x1 * s2) * SCALE_F;
        __nv_bfloat16 hi, lo;
        bsplit(r1, hi, lo); Qh[base + d] = hi; Ql[base + d] = lo;
        bsplit(r2, hi, lo); Qh[base + d + 64] = hi; Ql[base + d + 64] = lo;
    } else {
        const size_t base = (((size_t)b * SEQ + s) * NKV + (h - 28)) * HD;
        const float x1 = K[base + d];
        const float x2 = K[base + d + 64];
        const float r1 = x1 * c1 - x2 * s1;
        const float r2 = x2 * c2 + x1 * s2;
        __nv_bfloat16 hi, lo;
        bsplit(r1, hi, lo); Kh[base + d] = hi; Kl[base + d] = lo;
        bsplit(r2, hi, lo); Kh[base + d + 64] = hi; Kl[base + d + 64] = lo;
    }
}

// ---------------------------------------------------------------------------
// Tensor-core causal flash attention, bf16-split QK + tf32 PV.
// Q block 128 (8 warps x m16), KV block 64, double-buffered cp.async KV.
// smem (bytes):
//   Qhi [128 x 136 bf16] @ 0       (34816)
//   Qlo                  @ 34816   (34816)
//   stage s (s=0,1)      @ 69632 + s*69632:
//     Khi [64 x 136 bf16] @ +0      (17408)
//     Klo                 @ +17408  (17408)
//     V   [64 x 136 f32]  @ +34816  (34816)
// total 208896
// ---------------------------------------------------------------------------
#define QB 128
#define KB 64
#define FL_QL 34816
#define FL_ST 69632
#define FL_STSZ 69632
#define FL_KL 17408
#define FL_V  34816
#define FL_SMEM 208896
#define LDV 136

__global__ void __launch_bounds__(256, 1) flash_tc(
    const __nv_bfloat16* __restrict__ Qh, const __nv_bfloat16* __restrict__ Ql,
    const __nv_bfloat16* __restrict__ Kh, const __nv_bfloat16* __restrict__ Kl,
    const float* __restrict__ V, float* __restrict__ O)
{
    extern __shared__ char smc[];
    const uint32_t sb = (uint32_t)__cvta_generic_to_shared(smc);

    const int qb = blockIdx.x, h = blockIdx.y, b = blockIdx.z;
    const int kvh = h / NREP;
    const int tid = threadIdx.x;
    const int lane = tid & 31;
    const int w = tid >> 5;
    const int q4 = lane & 3;
    const int r4 = lane >> 2;

    // ---- issue Q hi/lo loads (group) ----
    {
        const char* qhg = (const char*)(Qh + (((size_t)b * SEQ + (size_t)qb * QB) * NH + h) * HD);
        const char* qlg = (const char*)(Ql + (((size_t)b * SEQ + (size_t)qb * QB) * NH + h) * HD);
#pragma unroll
        for (int i = 0; i < 16; i++) {
            const int id = tid + i * 256;
            if (id < 2048) {
                const int row = id >> 4, off = (id & 15) * 16;
                cp16(sb + row * 272 + off, qhg + (size_t)row * (NH * HD * 2) + off);
            } else {
                const int id2 = id - 2048;
                const int row = id2 >> 4, off = (id2 & 15) * 16;
                cp16(sb + FL_QL + row * 272 + off, qlg + (size_t)row * (NH * HD * 2) + off);
            }
        }
        cp_commit();
    }

    const char* khg0 = (const char*)(Kh + ((size_t)b * SEQ) * KV_HID + kvh * HD);
    const char* klg0 = (const char*)(Kl + ((size_t)b * SEQ) * KV_HID + kvh * HD);
    const char* vg0  = (const char*)(V + ((size_t)b * SEQ) * KV_HID + kvh * HD);

    auto issue_kv = [&](int kb, int s) {
        const uint32_t stb = sb + FL_ST + (uint32_t)s * FL_STSZ;
        const char* khg = khg0 + (size_t)kb * KB * 1024;   // bf16 row = 1024B stride
        const char* klg = klg0 + (size_t)kb * KB * 1024;
        const char* vg  = vg0 + (size_t)kb * KB * 2048;    // f32 row = 2048B stride
#pragma unroll
        for (int i = 0; i < 16; i++) {
            const int id = tid + i * 256;
            if (id < 1024) {
                const int row = id >> 4, off = (id & 15) * 16;
                cp16(stb + row * 272 + off, khg + (size_t)row * 1024 + off);
            } else if (id < 2048) {
                const int id2 = id - 1024;
                const int row = id2 >> 4, off = (id2 & 15) * 16;
                cp16(stb + FL_KL + row * 272 + off, klg + (size_t)row * 1024 + off);
            } else {
                const int id2 = id - 2048;
                const int row = id2 >> 5, off = (id2 & 31) * 16;
                cp16(stb + FL_V + row * 544 + off, vg + (size_t)row * 2048 + off);
            }
        }
        cp_commit();
    };

    const int kbmax = 2 * qb + 1;
    issue_kv(0, 0);
    issue_kv(1, 1);   // kbmax >= 1 always

    float oacc[16][4];
#pragma unroll
    for (int i = 0; i < 16; i++)
#pragma unroll
        for (int c = 0; c < 4; c++) oacc[i][c] = 0.f;
    float m0 = -1e30f, m1 = -1e30f, l0 = 0.f, l1 = 0.f;

    const int arow = w * 16 + r4;
    const int rg0 = qb * QB + arow;
    const int rg1 = rg0 + 8;

    const char* aH = smc + arow * 272 + q4 * 4;
    const char* aL = smc + FL_QL + arow * 272 + q4 * 4;

    for (int kb = 0; kb <= kbmax; kb++) {
        if (kb < kbmax) cp_wait<1>(); else cp_wait<0>();
        __syncthreads();

        const int cur = kb & 1;
        const char* Khp = smc + FL_ST + (size_t)cur * FL_STSZ;
        const char* Klp = Khp + FL_KL;
        const float* Vsp = (const float*)(Khp + FL_V);

        // ---- S = Q K^T, 3-term bf16 split ----
        float sacc[8][4];
#pragma unroll
        for (int nt = 0; nt < 8; nt++)
#pragma unroll
            for (int c = 0; c < 4; c++) sacc[nt][c] = 0.f;

#pragma unroll
        for (int kt = 0; kt < 8; kt++) {
            const int ko = kt * 32;
            uint32_t ah[4], al[4];
            ah[0] = *(const uint32_t*)(aH + ko);
            ah[1] = *(const uint32_t*)(aH + ko + 8 * 272);
            ah[2] = *(const uint32_t*)(aH + ko + 16);
            ah[3] = *(const uint32_t*)(aH + ko + 8 * 272 + 16);
            al[0] = *(const uint32_t*)(aL + ko);
            al[1] = *(const uint32_t*)(aL + ko + 8 * 272);
            al[2] = *(const uint32_t*)(aL + ko + 16);
            al[3] = *(const uint32_t*)(aL + ko + 8 * 272 + 16);
#pragma unroll
            for (int nt = 0; nt < 8; nt++) {
                const char* bp = Khp + (nt * 8 + r4) * 272 + q4 * 4 + ko;
                const char* bq = Klp + (nt * 8 + r4) * 272 + q4 * 4 + ko;
                const uint32_t bh0 = *(const uint32_t*)bp;
                const uint32_t bh1 = *(const uint32_t*)(bp + 16);
                const uint32_t bl0 = *(const uint32_t*)bq;
                const uint32_t bl1 = *(const uint32_t*)(bq + 16);
                mma_bf16(sacc[nt], ah, bh0, bh1);
                mma_bf16(sacc[nt], al, bh0, bh1);
                mma_bf16(sacc[nt], ah, bl0, bl1);
            }
        }

        // ---- mask + online softmax ----
        if (kb >= 2 * qb) {
            const int colb = kb * KB + 2 * q4;
#pragma unroll
            for (int nt = 0; nt < 8; nt++) {
                const int c0 = colb + nt * 8;
                if (c0 > rg0)     sacc[nt][0] = -1e30f;
                if (c0 + 1 > rg0) sacc[nt][1] = -1e30f;
                if (c0 > rg1)     sacc[nt][2] = -1e30f;
                if (c0 + 1 > rg1) sacc[nt][3] = -1e30f;
            }
        }
        float mb0 = -1e30f, mb1 = -1e30f;
#pragma unroll
        for (int nt = 0; nt < 8; nt++) {
            mb0 = fmaxf(mb0, fmaxf(sacc[nt][0], sacc[nt][1]));
            mb1 = fmaxf(mb1, fmaxf(sacc[nt][2], sacc[nt][3]));
        }
        mb0 = fmaxf(mb0, __shfl_xor_sync(0xffffffffu, mb0, 1));
        mb0 = fmaxf(mb0, __shfl_xor_sync(0xffffffffu, mb0, 2));
        mb1 = fmaxf(mb1, __shfl_xor_sync(0xffffffffu, mb1, 1));
        mb1 = fmaxf(mb1, __shfl_xor_sync(0xffffffffu, mb1, 2));

        const float mn0 = fmaxf(m0, mb0), mn1 = fmaxf(m1, mb1);
        const float a0 = __expf(m0 - mn0), a1 = __expf(m1 - mn1);
        m0 = mn0; m1 = mn1;

        float ls0 = 0.f, ls1 = 0.f;
#pragma unroll
        for (int nt = 0; nt < 8; nt++) {
            float p0 = to_tf32(__expf(sacc[nt][0] - mn0));
            float p1 = to_tf32(__expf(sacc[nt][1] - mn0));
            float p2 = to_tf32(__expf(sacc[nt][2] - mn1));
            float p3 = to_tf32(__expf(sacc[nt][3] - mn1));
            sacc[nt][0] = p0; sacc[nt][1] = p1;
            sacc[nt][2] = p2; sacc[nt][3] = p3;
            ls0 += p0 + p1; ls1 += p2 + p3;
        }
        ls0 += __shfl_xor_sync(0xffffffffu, ls0, 1);
        ls0 += __shfl_xor_sync(0xffffffffu, ls0, 2);
        ls1 += __shfl_xor_sync(0xffffffffu, ls1, 1);
        ls1 += __shfl_xor_sync(0xffffffffu, ls1, 2);
        l0 = l0 * a0 + ls0;
        l1 = l1 * a1 + ls1;

#pragma unroll
        for (int nt2 = 0; nt2 < 16; nt2++) {
            oacc[nt2][0] *= a0; oacc[nt2][1] *= a0;
            oacc[nt2][2] *= a1; oacc[nt2][3] *= a1;
        }

        // ---- O += P V (tf32) ----
        const int src0 = (lane & ~3) | (q4 >> 1);
        const int src1 = src0 | 2;
        const bool oddq = (q4 & 1);
#pragma unroll
        for (int kt2 = 0; kt2 < 8; kt2++) {
            const float t00 = __shfl_sync(0xffffffffu, sacc[kt2][0], src0);
            const float t01 = __shfl_sync(0xffffffffu, sacc[kt2][1], src0);
            const float t02 = __shfl_sync(0xffffffffu, sacc[kt2][2], src0);
            const float t03 = __shfl_sync(0xffffffffu, sacc[kt2][3], src0);
            const float t10 = __shfl_sync(0xffffffffu, sacc[kt2][0], src1);
            const float t11 = __shfl_sync(0xffffffffu, sacc[kt2][1], src1);
            const float t12 = __shfl_sync(0xffffffffu, sacc[kt2][2], src1);
            const float t13 = __shfl_sync(0xffffffffu, sacc[kt2][3], src1);
            float pa[4];
            pa[0] = oddq ? t01 : t00;
            pa[1] = oddq ? t03 : t02;
            pa[2] = oddq ? t11 : t10;
            pa[3] = oddq ? t13 : t12;
            const float* vrow = Vsp + (kt2 * 8 + q4) * LDV + r4;
#pragma unroll
            for (int nt2 = 0; nt2 < 16; nt2++) {
                mma_tf32f(oacc[nt2], pa, vrow[nt2 * 8], vrow[nt2 * 8 + 4 * LDV]);
            }
        }

        __syncthreads();
        if (kb + 2 <= kbmax) issue_kv(kb + 2, cur);
    }

    // epilogue
    const float inv0 = 1.f / l0, inv1 = 1.f / l1;
    float* o0 = O + (((size_t)b * SEQ + rg0) * NH + h) * HD;
    float* o1 = O + (((size_t)b * SEQ + rg1) * NH + h) * HD;
#pragma unroll
    for (int nt2 = 0; nt2 < 16; nt2++) {
        const int col = nt2 * 8 + 2 * q4;
        *(float2*)(o0 + col) = make_float2(oacc[nt2][0] * inv0, oacc[nt2][1] * inv0);
        *(float2*)(o1 + col) = make_float2(oacc[nt2][2] * inv1, oacc[nt2][3] * inv1);
    }
}

// ---------------------------------------------------------------------------
extern "C" void kernel_launch(void* const* d_in, const int* in_sizes, int n_in,
                              void* d_out, int out_size)
{
    const float* hs   = (const float*)d_in[0];
    const float* cosT = (const float*)d_in[1];
    const float* sinT = (const float*)d_in[2];
    const float* q_w = (const float*)d_in[4];
    const float* q_b = (const float*)d_in[5];
    const float* k_w = (const float*)d_in[6];
    const float* k_b = (const float*)d_in[7];
    const float* v_w = (const float*)d_in[8];
    const float* v_b = (const float*)d_in[9];
    const float* o_w = (const float*)d_in[10];
    float* out = (float*)d_out;

    float *Qb, *Kb, *Vb, *Ab;
    __nv_bfloat16 *Qhi, *Qlo, *Khi, *Klo;
    cudaGetSymbolAddress((void**)&Qb, g_Q);
    cudaGetSymbolAddress((void**)&Kb, g_K);
    cudaGetSymbolAddress((void**)&Vb, g_V);
    cudaGetSymbolAddress((void**)&Ab, g_A);
    cudaGetSymbolAddress((void**)&Qhi, g_Qhi);
    cudaGetSymbolAddress((void**)&Qlo, g_Qlo);
    cudaGetSymbolAddress((void**)&Khi, g_Khi);
    cudaGetSymbolAddress((void**)&Klo, g_Klo);

    // Streams/events: created once on the (uncaptured) correctness call.
    static cudaStream_t sK = nullptr, sV = nullptr;
    static cudaEvent_t eFork = nullptr, eK = nullptr, eV = nullptr;
    if (!sK) {
        cudaStreamCreateWithFlags(&sK, cudaStreamNonBlocking);
        cudaStreamCreateWithFlags(&sV, cudaStreamNonBlocking);
        cudaEventCreateWithFlags(&eFork, cudaEventDisableTiming);
        cudaEventCreateWithFlags(&eK, cudaEventDisableTiming);
        cudaEventCreateWithFlags(&eV, cudaEventDisableTiming);
        cudaFuncSetAttribute(flash_tc, cudaFuncAttributeMaxDynamicSharedMemorySize, FL_SMEM);
    }

    // Fork: K-proj and V-proj run concurrently with Q-proj.
    cudaEventRecord(eFork, 0);
    cudaStreamWaitEvent(sK, eFork, 0);
    cudaStreamWaitEvent(sV, eFork, 0);

    tf32_gemm_nt<<<dim3(HID / 128, M_ROWS / 128), 256, 0, 0>>>(
        hs, q_w, q_b, Qb, M_ROWS, HID, HID, 0);
    tf32_gemm_nt<<<dim3(KV_HID / 128, M_ROWS / 128), 256, 0, sK>>>(
        hs, k_w, k_b, Kb, M_ROWS, KV_HID, HID, 0);
    tf32_gemm_nt<<<dim3(KV_HID / 128, M_ROWS / 128), 256, 0, sV>>>(
        hs, v_w, v_b, Vb, M_ROWS, KV_HID, HID, 1);   // V rounded to tf32

    cudaEventRecord(eK, sK);
    cudaEventRecord(eV, sV);
    cudaStreamWaitEvent(0, eK, 0);
    cudaStreamWaitEvent(0, eV, 0);

    // RoPE + bf16 hi/lo split of Q (prescaled) and K
    rope_split<<<(BATCH * SEQ * 32 * 64) / 256, 256>>>(
        Qb, Kb, cosT, sinT, Qhi, Qlo, Khi, Klo);

    // Tensor-core causal flash attention
    flash_tc<<<dim3(SEQ / QB, NH, BATCH), 256, FL_SMEM>>>(
        Qhi, Qlo, Khi, Klo, Vb, Ab);

    // Output projection
    tf32_gemm_nt<<<dim3(HID / 128, M_ROWS / 128), 256>>>(
        Ab, o_w, nullptr, out, M_ROWS, HID, HID, 0);
}

// round 6
// speedup vs baseline: 5.2820x; 1.0081x over previous
#include <cuda_runtime.h>
#include <cuda_bf16.h>
#include <cstdint>

// Problem constants
#define BATCH 2
#define SEQ 2048
#define HID 3584
#define NH 28
#define NKV 4
#define HD 128
#define NREP 7
#define M_ROWS (BATCH * SEQ)           // 4096
#define KV_HID (NKV * HD)              // 512
#define SCALE_F 0.08838834764831845f   // 128^-0.5

// Scratch (device globals; allocation is forbidden)
__device__ float g_Q[(size_t)M_ROWS * HID];
__device__ float g_K[(size_t)M_ROWS * KV_HID];
__device__ float g_V[(size_t)M_ROWS * KV_HID];
__device__ float g_A[(size_t)M_ROWS * HID];
__device__ __nv_bfloat16 g_Qhi[(size_t)M_ROWS * HID];
__device__ __nv_bfloat16 g_Qlo[(size_t)M_ROWS * HID];
__device__ __nv_bfloat16 g_Khi[(size_t)M_ROWS * KV_HID];
__device__ __nv_bfloat16 g_Klo[(size_t)M_ROWS * KV_HID];
// tf32-rounded (rna) copies: GEMM fragments need no cvt in the inner loop
__device__ float g_HSr[(size_t)M_ROWS * HID];
__device__ float g_QWr[(size_t)HID * HID];
__device__ float g_KWr[(size_t)KV_HID * HID];
__device__ float g_VWr[(size_t)KV_HID * HID];
__device__ float g_OWr[(size_t)HID * HID];

// ---------------------------------------------------------------------------
// Helpers
// ---------------------------------------------------------------------------
__device__ __forceinline__ float to_tf32(float x) {
    asm("cvt.rna.tf32.f32 %0, %0;" : "+f"(x));
    return x;
}
__device__ __forceinline__ void ldmx4(uint32_t& r0, uint32_t& r1, uint32_t& r2,
                                      uint32_t& r3, uint32_t addr) {
    asm volatile("ldmatrix.sync.aligned.m8n8.x4.shared.b16 {%0,%1,%2,%3}, [%4];"
                 : "=r"(r0), "=r"(r1), "=r"(r2), "=r"(r3) : "r"(addr));
}
__device__ __forceinline__ void mma_tf32(float* c, const uint32_t* a,
                                         uint32_t b0, uint32_t b1) {
    asm volatile(
        "mma.sync.aligned.m16n8k8.row.col.f32.tf32.tf32.f32 "
        "{%0,%1,%2,%3}, {%4,%5,%6,%7}, {%8,%9}, {%0,%1,%2,%3};"
        : "+f"(c[0]), "+f"(c[1]), "+f"(c[2]), "+f"(c[3])
        : "r"(a[0]), "r"(a[1]), "r"(a[2]), "r"(a[3]), "r"(b0), "r"(b1));
}
__device__ __forceinline__ void mma_tf32f(float* c, const float* a,
                                          float b0f, float b1f) {
    uint32_t a0 = __float_as_uint(a[0]), a1 = __float_as_uint(a[1]);
    uint32_t a2 = __float_as_uint(a[2]), a3 = __float_as_uint(a[3]);
    uint32_t b0 = __float_as_uint(b0f), b1 = __float_as_uint(b1f);
    asm volatile(
        "mma.sync.aligned.m16n8k8.row.col.f32.tf32.tf32.f32 "
        "{%0,%1,%2,%3}, {%4,%5,%6,%7}, {%8,%9}, {%0,%1,%2,%3};"
        : "+f"(c[0]), "+f"(c[1]), "+f"(c[2]), "+f"(c[3])
        : "r"(a0), "r"(a1), "r"(a2), "r"(a3), "r"(b0), "r"(b1));
}
__device__ __forceinline__ void mma_bf16(float* c, const uint32_t* a,
                                         uint32_t b0, uint32_t b1) {
    asm volatile(
        "mma.sync.aligned.m16n8k16.row.col.f32.bf16.bf16.f32 "
        "{%0,%1,%2,%3}, {%4,%5,%6,%7}, {%8,%9}, {%0,%1,%2,%3};"
        : "+f"(c[0]), "+f"(c[1]), "+f"(c[2]), "+f"(c[3])
        : "r"(a[0]), "r"(a[1]), "r"(a[2]), "r"(a[3]), "r"(b0), "r"(b1));
}
__device__ __forceinline__ void cp16(uint32_t dst, const void* src) {
    asm volatile("cp.async.cg.shared.global [%0], [%1], 16;" :: "r"(dst), "l"(src));
}
__device__ __forceinline__ void cp_commit() {
    asm volatile("cp.async.commit_group;");
}
template <int N>
__device__ __forceinline__ void cp_wait() {
    asm volatile("cp.async.wait_group %0;" :: "n"(N));
}
__device__ __forceinline__ void bsplit(float x, __nv_bfloat16& hi, __nv_bfloat16& lo) {
    hi = __float2bfloat16(x);
    lo = __float2bfloat16(x - __bfloat162float(hi));
}

// ---------------------------------------------------------------------------
// Elementwise tf32 (rna) rounding pass
// ---------------------------------------------------------------------------
__global__ void round_tf32_k(const float4* __restrict__ in, float4* __restrict__ out, int n4)
{
    const int i = blockIdx.x * blockDim.x + threadIdx.x;
    if (i < n4) {
        float4 v = in[i];
        v.x = to_tf32(v.x); v.y = to_tf32(v.y);
        v.z = to_tf32(v.z); v.w = to_tf32(v.w);
        out[i] = v;
    }
}

// ---------------------------------------------------------------------------
// TF32 tensor-core GEMM: C[M,N] = A[M,K] @ W[N,K]^T + bias
// Inputs must be PRE-ROUNDED to tf32 (rna). No cvt in the inner loop.
// 128x128 tile, BK=16, 256 threads, 3-stage cp.async pipeline.
// rnd!=0: round outputs to tf32 in epilogue (used for V).
// ---------------------------------------------------------------------------
#define LDA 20
#define BUF_FLOATS (128 * LDA)
#define BUF_BYTES (BUF_FLOATS * 4)

__global__ void __launch_bounds__(256) tf32_gemm_nt(
    const float* __restrict__ A, const float* __restrict__ W,
    const float* __restrict__ bias, float* __restrict__ C,
    int M, int N, int K, int rnd)
{
    __shared__ __align__(16) float As[3][BUF_FLOATS];
    __shared__ __align__(16) float Bs[3][BUF_FLOATS];

    const int bm = blockIdx.y * 128;
    const int bn = blockIdx.x * 128;
    const int tid = threadIdx.x;
    const int lane = tid & 31;
    const int wid = tid >> 5;
    const int wm = wid >> 2;
    const int wn = wid & 3;
    const int g = lane >> 3;
    const int lr = lane & 7;

    const uint32_t sA = (uint32_t)__cvta_generic_to_shared(&As[0][0]);
    const uint32_t sB = (uint32_t)__cvta_generic_to_shared(&Bs[0][0]);

    uint32_t aBase[4], bBase[2];
#pragma unroll
    for (int m = 0; m < 4; m++) {
        int row = wm * 64 + m * 16 + lr + (g & 1) * 8;
        int col = (g >> 1) * 4;
        aBase[m] = sA + (row * LDA + col) * 4;
    }
#pragma unroll
    for (int p = 0; p < 2; p++) {
        int row = wn * 32 + p * 16 + lr + (g >> 1) * 8;
        int col = (g & 1) * 4;
        bBase[p] = sB + (row * LDA + col) * 4;
    }

    const int lrow = tid >> 2;
    const int lcol = (tid & 3) << 2;
    const float* Ap = A + (size_t)(bm + lrow) * K + lcol;
    const float* Wp = W + (size_t)(bn + lrow) * K + lcol;
    const uint32_t smoff = (lrow * LDA + lcol) * 4;
    const uint32_t smoff2 = smoff + 64 * LDA * 4;

    auto issue = [&](int t, int s) {
        const uint32_t da = sA + (uint32_t)s * BUF_BYTES;
        const uint32_t db = sB + (uint32_t)s * BUF_BYTES;
        const float* ap = Ap + t * 16;
        const float* wp = Wp + t * 16;
        cp16(da + smoff, ap);
        cp16(da + smoff2, ap + (size_t)64 * K);
        cp16(db + smoff, wp);
        cp16(db + smoff2, wp + (size_t)64 * K);
        cp_commit();
    };

    float acc[4][4][4];
#pragma unroll
    for (int m = 0; m < 4; m++)
#pragma unroll
        for (int n = 0; n < 4; n++)
#pragma unroll
            for (int i = 0; i < 4; i++) acc[m][n][i] = 0.f;

    const int T = K / 16;
    issue(0, 0);
    issue(1, 1);

    for (int t = 0; t < T; t++) {
        if (t + 1 < T) cp_wait<1>(); else cp_wait<0>();
        __syncthreads();
        if (t + 2 < T) issue(t + 2, (t + 2) % 3);

        const uint32_t bufoff = (uint32_t)(t % 3) * BUF_BYTES;
#pragma unroll
        for (int ks = 0; ks < 16; ks += 8) {
            uint32_t afr[4][4];
#pragma unroll
            for (int m = 0; m < 4; m++)
                ldmx4(afr[m][0], afr[m][1], afr[m][2], afr[m][3],
                      aBase[m] + bufoff + ks * 4);
#pragma unroll
            for (int p = 0; p < 2; p++) {
                uint32_t bf0, bf1, bf2, bf3;
                ldmx4(bf0, bf1, bf2, bf3, bBase[p] + bufoff + ks * 4);
#pragma unroll
                for (int m = 0; m < 4; m++) {
                    mma_tf32(acc[m][2 * p + 0], afr[m], bf0, bf1);
                    mma_tf32(acc[m][2 * p + 1], afr[m], bf2, bf3);
                }
            }
        }
    }

#pragma unroll
    for (int m = 0; m < 4; m++) {
        const int row = bm + wm * 64 + m * 16 + (lane >> 2);
#pragma unroll
        for (int n = 0; n < 4; n++) {
            const int col = bn + wn * 32 + n * 8 + (lane & 3) * 2;
            float bx = 0.f, by = 0.f;
            if (bias) { bx = bias[col]; by = bias[col + 1]; }
            float2 v0 = make_float2(acc[m][n][0] + bx, acc[m][n][1] + by);
            float2 v1 = make_float2(acc[m][n][2] + bx, acc[m][n][3] + by);
            if (rnd) {
                v0.x = to_tf32(v0.x); v0.y = to_tf32(v0.y);
                v1.x = to_tf32(v1.x); v1.y = to_tf32(v1.y);
            }
            *(float2*)&C[(size_t)row * N + col] = v0;
            *(float2*)&C[(size_t)(row + 8) * N + col] = v1;
        }
    }
}

// ---------------------------------------------------------------------------
// RoPE + bf16 hi/lo split. Q additionally prescaled by SCALE_F.
// ---------------------------------------------------------------------------
__global__ void rope_split(const float* __restrict__ Q, const float* __restrict__ K,
                           const float* __restrict__ cosT, const float* __restrict__ sinT,
                           __nv_bfloat16* __restrict__ Qh, __nv_bfloat16* __restrict__ Ql,
                           __nv_bfloat16* __restrict__ Kh, __nv_bfloat16* __restrict__ Kl)
{
    const int idx = blockIdx.x * blockDim.x + threadIdx.x;
    const int d = idx & 63;
    const int h = (idx >> 6) & 31;
    const int s = (idx >> 11) & 2047;
    const int b = idx >> 22;

    const float c1 = cosT[s * 128 + d];
    const float s1 = sinT[s * 128 + d];
    const float c2 = cosT[s * 128 + d + 64];
    const float s2 = sinT[s * 128 + d + 64];

    if (h < 28) {
        const size_t base = (((size_t)b * SEQ + s) * NH + h) * HD;
        const float x1 = Q[base + d];
        const float x2 = Q[base + d + 64];
        const float r1 = (x1 * c1 - x2 * s1) * SCALE_F;
        const float r2 = (x2 * c2 + x1 * s2) * SCALE_F;
        __nv_bfloat16 hi, lo;
        bsplit(r1, hi, lo); Qh[base + d] = hi; Ql[base + d] = lo;
        bsplit(r2, hi, lo); Qh[base + d + 64] = hi; Ql[base + d + 64] = lo;
    } else {
        const size_t base = (((size_t)b * SEQ + s) * NKV + (h - 28)) * HD;
        const float x1 = K[base + d];
        const float x2 = K[base + d + 64];
        const float r1 = x1 * c1 - x2 * s1;
        const float r2 = x2 * c2 + x1 * s2;
        __nv_bfloat16 hi, lo;
        bsplit(r1, hi, lo); Kh[base + d] = hi; Kl[base + d] = lo;
        bsplit(r2, hi, lo); Kh[base + d + 64] = hi; Kl[base + d + 64] = lo;
    }
}

// ---------------------------------------------------------------------------
// Tensor-core causal flash attention (bf16-split QK + tf32 PV), as R4.
// Epilogue writes tf32-rounded output (feeds the O-projection directly).
// ---------------------------------------------------------------------------
#define QB 128
#define KB 64
#define FL_QL 34816
#define FL_ST 69632
#define FL_STSZ 69632
#define FL_KL 17408
#define FL_V  34816
#define FL_SMEM 208896
#define LDV 136

__global__ void __launch_bounds__(256, 1) flash_tc(
    const __nv_bfloat16* __restrict__ Qh, const __nv_bfloat16* __restrict__ Ql,
    const __nv_bfloat16* __restrict__ Kh, const __nv_bfloat16* __restrict__ Kl,
    const float* __restrict__ V, float* __restrict__ O)
{
    extern __shared__ char smc[];
    const uint32_t sb = (uint32_t)__cvta_generic_to_shared(smc);

    const int qb = blockIdx.x, h = blockIdx.y, b = blockIdx.z;
    const int kvh = h / NREP;
    const int tid = threadIdx.x;
    const int lane = tid & 31;
    const int w = tid >> 5;
    const int q4 = lane & 3;
    const int r4 = lane >> 2;

    {
        const char* qhg = (const char*)(Qh + (((size_t)b * SEQ + (size_t)qb * QB) * NH + h) * HD);
        const char* qlg = (const char*)(Ql + (((size_t)b * SEQ + (size_t)qb * QB) * NH + h) * HD);
#pragma unroll
        for (int i = 0; i < 16; i++) {
            const int id = tid + i * 256;
            if (id < 2048) {
                const int row = id >> 4, off = (id & 15) * 16;
                cp16(sb + row * 272 + off, qhg + (size_t)row * (NH * HD * 2) + off);
            } else {
                const int id2 = id - 2048;
                const int row = id2 >> 4, off = (id2 & 15) * 16;
                cp16(sb + FL_QL + row * 272 + off, qlg + (size_t)row * (NH * HD * 2) + off);
            }
        }
        cp_commit();
    }

    const char* khg0 = (const char*)(Kh + ((size_t)b * SEQ) * KV_HID + kvh * HD);
    const char* klg0 = (const char*)(Kl + ((size_t)b * SEQ) * KV_HID + kvh * HD);
    const char* vg0  = (const char*)(V + ((size_t)b * SEQ) * KV_HID + kvh * HD);

    auto issue_kv = [&](int kb, int s) {
        const uint32_t stb = sb + FL_ST + (uint32_t)s * FL_STSZ;
        const char* khg = khg0 + (size_t)kb * KB * 1024;
        const char* klg = klg0 + (size_t)kb * KB * 1024;
        const char* vg  = vg0 + (size_t)kb * KB * 2048;
#pragma unroll
        for (int i = 0; i < 16; i++) {
            const int id = tid + i * 256;
            if (id < 1024) {
                const int row = id >> 4, off = (id & 15) * 16;
                cp16(stb + row * 272 + off, khg + (size_t)row * 1024 + off);
            } else if (id < 2048) {
                const int id2 = id - 1024;
                const int row = id2 >> 4, off = (id2 & 15) * 16;
                cp16(stb + FL_KL + row * 272 + off, klg + (size_t)row * 1024 + off);
            } else {
                const int id2 = id - 2048;
                const int row = id2 >> 5, off = (id2 & 31) * 16;
                cp16(stb + FL_V + row * 544 + off, vg + (size_t)row * 2048 + off);
            }
        }
        cp_commit();
    };

    const int kbmax = 2 * qb + 1;
    issue_kv(0, 0);
    issue_kv(1, 1);

    float oacc[16][4];
#pragma unroll
    for (int i = 0; i < 16; i++)
#pragma unroll
        for (int c = 0; c < 4; c++) oacc[i][c] = 0.f;
    float m0 = -1e30f, m1 = -1e30f, l0 = 0.f, l1 = 0.f;

    const int arow = w * 16 + r4;
    const int rg0 = qb * QB + arow;
    const int rg1 = rg0 + 8;

    const char* aH = smc + arow * 272 + q4 * 4;
    const char* aL = smc + FL_QL + arow * 272 + q4 * 4;

    for (int kb = 0; kb <= kbmax; kb++) {
        if (kb < kbmax) cp_wait<1>(); else cp_wait<0>();
        __syncthreads();

        const int cur = kb & 1;
        const char* Khp = smc + FL_ST + (size_t)cur * FL_STSZ;
        const char* Klp = Khp + FL_KL;
        const float* Vsp = (const float*)(Khp + FL_V);

        float sacc[8][4];
#pragma unroll
        for (int nt = 0; nt < 8; nt++)
#pragma unroll
            for (int c = 0; c < 4; c++) sacc[nt][c] = 0.f;

#pragma unroll
        for (int kt = 0; kt < 8; kt++) {
            const int ko = kt * 32;
            uint32_t ah[4], al[4];
            ah[0] = *(const uint32_t*)(aH + ko);
            ah[1] = *(const uint32_t*)(aH + ko + 8 * 272);
            ah[2] = *(const uint32_t*)(aH + ko + 16);
            ah[3] = *(const uint32_t*)(aH + ko + 8 * 272 + 16);
            al[0] = *(const uint32_t*)(aL + ko);
            al[1] = *(const uint32_t*)(aL + ko + 8 * 272);
            al[2] = *(const uint32_t*)(aL + ko + 16);
            al[3] = *(const uint32_t*)(aL + ko + 8 * 272 + 16);
#pragma unroll
            for (int nt = 0; nt < 8; nt++) {
                const char* bp = Khp + (nt * 8 + r4) * 272 + q4 * 4 + ko;
                const char* bq = Klp + (nt * 8 + r4) * 272 + q4 * 4 + ko;
                const uint32_t bh0 = *(const uint32_t*)bp;
                const uint32_t bh1 = *(const uint32_t*)(bp + 16);
                const uint32_t bl0 = *(const uint32_t*)bq;
                const uint32_t bl1 = *(const uint32_t*)(bq + 16);
                mma_bf16(sacc[nt], ah, bh0, bh1);
                mma_bf16(sacc[nt], al, bh0, bh1);
                mma_bf16(sacc[nt], ah, bl0, bl1);
            }
        }

        if (kb >= 2 * qb) {
            const int colb = kb * KB + 2 * q4;
#pragma unroll
            for (int nt = 0; nt < 8; nt++) {
                const int c0 = colb + nt * 8;
                if (c0 > rg0)     sacc[nt][0] = -1e30f;
                if (c0 + 1 > rg0) sacc[nt][1] = -1e30f;
                if (c0 > rg1)     sacc[nt][2] = -1e30f;
                if (c0 + 1 > rg1) sacc[nt][3] = -1e30f;
            }
        }
        float mb0 = -1e30f, mb1 = -1e30f;
#pragma unroll
        for (int nt = 0; nt < 8; nt++) {
            mb0 = fmaxf(mb0, fmaxf(sacc[nt][0], sacc[nt][1]));
            mb1 = fmaxf(mb1, fmaxf(sacc[nt][2], sacc[nt][3]));
        }
        mb0 = fmaxf(mb0, __shfl_xor_sync(0xffffffffu, mb0, 1));
        mb0 = fmaxf(mb0, __shfl_xor_sync(0xffffffffu, mb0, 2));
        mb1 = fmaxf(mb1, __shfl_xor_sync(0xffffffffu, mb1, 1));
        mb1 = fmaxf(mb1, __shfl_xor_sync(0xffffffffu, mb1, 2));

        const float mn0 = fmaxf(m0, mb0), mn1 = fmaxf(m1, mb1);
        const float a0 = __expf(m0 - mn0), a1 = __expf(m1 - mn1);
        m0 = mn0; m1 = mn1;

        float ls0 = 0.f, ls1 = 0.f;
#pragma unroll
        for (int nt = 0; nt < 8; nt++) {
            float p0 = to_tf32(__expf(sacc[nt][0] - mn0));
            float p1 = to_tf32(__expf(sacc[nt][1] - mn0));
            float p2 = to_tf32(__expf(sacc[nt][2] - mn1));
            float p3 = to_tf32(__expf(sacc[nt][3] - mn1));
            sacc[nt][0] = p0; sacc[nt][1] = p1;
            sacc[nt][2] = p2; sacc[nt][3] = p3;
            ls0 += p0 + p1; ls1 += p2 + p3;
        }
        ls0 += __shfl_xor_sync(0xffffffffu, ls0, 1);
        ls0 += __shfl_xor_sync(0xffffffffu, ls0, 2);
        ls1 += __shfl_xor_sync(0xffffffffu, ls1, 1);
        ls1 += __shfl_xor_sync(0xffffffffu, ls1, 2);
        l0 = l0 * a0 + ls0;
        l1 = l1 * a1 + ls1;

#pragma unroll
        for (int nt2 = 0; nt2 < 16; nt2++) {
            oacc[nt2][0] *= a0; oacc[nt2][1] *= a0;
            oacc[nt2][2] *= a1; oacc[nt2][3] *= a1;
        }

        const int src0 = (lane & ~3) | (q4 >> 1);
        const int src1 = src0 | 2;
        const bool oddq = (q4 & 1);
#pragma unroll
        for (int kt2 = 0; kt2 < 8; kt2++) {
            const float t00 = __shfl_sync(0xffffffffu, sacc[kt2][0], src0);
            const float t01 = __shfl_sync(0xffffffffu, sacc[kt2][1], src0);
            const float t02 = __shfl_sync(0xffffffffu, sacc[kt2][2], src0);
            const float t03 = __shfl_sync(0xffffffffu, sacc[kt2][3], src0);
            const float t10 = __shfl_sync(0xffffffffu, sacc[kt2][0], src1);
            const float t11 = __shfl_sync(0xffffffffu, sacc[kt2][1], src1);
            const float t12 = __shfl_sync(0xffffffffu, sacc[kt2][2], src1);
            const float t13 = __shfl_sync(0xffffffffu, sacc[kt2][3], src1);
            float pa[4];
            pa[0] = oddq ? t01 : t00;
            pa[1] = oddq ? t03 : t02;
            pa[2] = oddq ? t11 : t10;
            pa[3] = oddq ? t13 : t12;
            const float* vrow = Vsp + (kt2 * 8 + q4) * LDV + r4;
#pragma unroll
            for (int nt2 = 0; nt2 < 16; nt2++) {
                mma_tf32f(oacc[nt2], pa, vrow[nt2 * 8], vrow[nt2 * 8 + 4 * LDV]);
            }
        }

        __syncthreads();
        if (kb + 2 <= kbmax) issue_kv(kb + 2, cur);
    }

    const float inv0 = 1.f / l0, inv1 = 1.f / l1;
    float* o0 = O + (((size_t)b * SEQ + rg0) * NH + h) * HD;
    float* o1 = O + (((size_t)b * SEQ + rg1) * NH + h) * HD;
#pragma unroll
    for (int nt2 = 0; nt2 < 16; nt2++) {
        const int col = nt2 * 8 + 2 * q4;
        *(float2*)(o0 + col) = make_float2(to_tf32(oacc[nt2][0] * inv0),
                                           to_tf32(oacc[nt2][1] * inv0));
        *(float2*)(o1 + col) = make_float2(to_tf32(oacc[nt2][2] * inv1),
                                           to_tf32(oacc[nt2][3] * inv1));
    }
}

// ---------------------------------------------------------------------------
extern "C" void kernel_launch(void* const* d_in, const int* in_sizes, int n_in,
                              void* d_out, int out_size)
{
    const float* hs   = (const float*)d_in[0];
    const float* cosT = (const float*)d_in[1];
    const float* sinT = (const float*)d_in[2];
    const float* q_w = (const float*)d_in[4];
    const float* q_b = (const float*)d_in[5];
    const float* k_w = (const float*)d_in[6];
    const float* k_b = (const float*)d_in[7];
    const float* v_w = (const float*)d_in[8];
    const float* v_b = (const float*)d_in[9];
    const float* o_w = (const float*)d_in[10];
    float* out = (float*)d_out;

    float *Qb, *Kb, *Vb, *Ab, *HSr, *QWr, *KWr, *VWr, *OWr;
    __nv_bfloat16 *Qhi, *Qlo, *Khi, *Klo;
    cudaGetSymbolAddress((void**)&Qb, g_Q);
    cudaGetSymbolAddress((void**)&Kb, g_K);
    cudaGetSymbolAddress((void**)&Vb, g_V);
    cudaGetSymbolAddress((void**)&Ab, g_A);
    cudaGetSymbolAddress((void**)&HSr, g_HSr);
    cudaGetSymbolAddress((void**)&QWr, g_QWr);
    cudaGetSymbolAddress((void**)&KWr, g_KWr);
    cudaGetSymbolAddress((void**)&VWr, g_VWr);
    cudaGetSymbolAddress((void**)&OWr, g_OWr);
    cudaGetSymbolAddress((void**)&Qhi, g_Qhi);
    cudaGetSymbolAddress((void**)&Qlo, g_Qlo);
    cudaGetSymbolAddress((void**)&Khi, g_Khi);
    cudaGetSymbolAddress((void**)&Klo, g_Klo);

    static cudaStream_t sK = nullptr, sV = nullptr;
    static cudaEvent_t eFork = nullptr, eK = nullptr, eV = nullptr, eOW = nullptr;
    if (!sK) {
        cudaStreamCreateWithFlags(&sK, cudaStreamNonBlocking);
        cudaStreamCreateWithFlags(&sV, cudaStreamNonBlocking);
        cudaEventCreateWithFlags(&eFork, cudaEventDisableTiming);
        cudaEventCreateWithFlags(&eK, cudaEventDisableTiming);
        cudaEventCreateWithFlags(&eV, cudaEventDisableTiming);
        cudaEventCreateWithFlags(&eOW, cudaEventDisableTiming);
        cudaFuncSetAttribute(flash_tc, cudaFuncAttributeMaxDynamicSharedMemorySize, FL_SMEM);
    }

    const int nt = 256;

    // Round hidden_states on main stream (everyone needs it)
    {
        const int n4 = M_ROWS * HID / 4;
        round_tf32_k<<<(n4 + nt - 1) / nt, nt>>>((const float4*)hs, (float4*)HSr, n4);
    }

    // Fork
    cudaEventRecord(eFork, 0);
    cudaStreamWaitEvent(sK, eFork, 0);
    cudaStreamWaitEvent(sV, eFork, 0);

    // Q path (main stream): round QW, then Q-proj
    {
        const int n4 = HID * HID / 4;
        round_tf32_k<<<(n4 + nt - 1) / nt, nt>>>((const float4*)q_w, (float4*)QWr, n4);
    }
    tf32_gemm_nt<<<dim3(HID / 128, M_ROWS / 128), 256, 0, 0>>>(
        HSr, QWr, q_b, Qb, M_ROWS, HID, HID, 0);

    // K path (stream sK)
    {
        const int n4 = KV_HID * HID / 4;
        round_tf32_k<<<(n4 + nt - 1) / nt, nt, 0, sK>>>((const float4*)k_w, (float4*)KWr, n4);
    }
    tf32_gemm_nt<<<dim3(KV_HID / 128, M_ROWS / 128), 256, 0, sK>>>(
        HSr, KWr, k_b, Kb, M_ROWS, KV_HID, HID, 0);
    cudaEventRecord(eK, sK);

    // V path (stream sV); V output tf32-rounded for the PV mma
    {
        const int n4 = KV_HID * HID / 4;
        round_tf32_k<<<(n4 + nt - 1) / nt, nt, 0, sV>>>((const float4*)v_w, (float4*)VWr, n4);
    }
    tf32_gemm_nt<<<dim3(KV_HID / 128, M_ROWS / 128), 256, 0, sV>>>(
        HSr, VWr, v_b, Vb, M_ROWS, KV_HID, HID, 1);
    cudaEventRecord(eV, sV);

    // Round O-proj weight on sV after V gemm (overlaps rope + flash)
    {
        const int n4 = HID * HID / 4;
        round_tf32_k<<<(n4 + nt - 1) / nt, nt, 0, sV>>>((const float4*)o_w, (float4*)OWr, n4);
    }
    cudaEventRecord(eOW, sV);

    // Join K,V for rope
    cudaStreamWaitEvent(0, eK, 0);
    cudaStreamWaitEvent(0, eV, 0);

    // RoPE + bf16 hi/lo split
    rope_split<<<(BATCH * SEQ * 32 * 64) / 256, 256>>>(
        Qb, Kb, cosT, sinT, Qhi, Qlo, Khi, Klo);

    // Flash attention (epilogue writes tf32-rounded A)
    flash_tc<<<dim3(SEQ / QB, NH, BATCH), 256, FL_SMEM>>>(
        Qhi, Qlo, Khi, Klo, Vb, Ab);

    // Output projection (A already rounded by flash; OW rounded on sV)
    cudaStreamWaitEvent(0, eOW, 0);
    tf32_gemm_nt<<<dim3(HID / 128, M_ROWS / 128), 256>>>(
        Ab, OWr, nullptr, out, M_ROWS, HID, HID, 0);
}

// round 8
// speedup vs baseline: 5.8759x; 1.1124x over previous
#include <cuda_runtime.h>
#include <cuda_bf16.h>
#include <cstdint>

// Problem constants
#define BATCH 2
#define SEQ 2048
#define HID 3584
#define NH 28
#define NKV 4
#define HD 128
#define NREP 7
#define M_ROWS (BATCH * SEQ)           // 4096
#define KV_HID (NKV * HD)              // 512
#define SCALE_F 0.08838834764831845f   // 128^-0.5

// Scratch (device globals; allocation is forbidden)
__device__ float g_Q[(size_t)M_ROWS * HID];
__device__ float g_K[(size_t)M_ROWS * KV_HID];
__device__ float g_V[(size_t)M_ROWS * KV_HID];
__device__ float g_A[(size_t)M_ROWS * HID];
__device__ __nv_bfloat16 g_Qhi[(size_t)M_ROWS * HID];
__device__ __nv_bfloat16 g_Qlo[(size_t)M_ROWS * HID];
__device__ __nv_bfloat16 g_Khi[(size_t)M_ROWS * KV_HID];
__device__ __nv_bfloat16 g_Klo[(size_t)M_ROWS * KV_HID];
// tf32-rounded (rna) copies
__device__ float g_HSr[(size_t)M_ROWS * HID];
__device__ float g_QWr[(size_t)HID * HID];
__device__ float g_KWr[(size_t)KV_HID * HID];
__device__ float g_VWr[(size_t)KV_HID * HID];
__device__ float g_OWr[(size_t)HID * HID];

// ---------------------------------------------------------------------------
// Helpers
// ---------------------------------------------------------------------------
__device__ __forceinline__ float to_tf32(float x) {
    asm("cvt.rna.tf32.f32 %0, %0;" : "+f"(x));
    return x;
}
__device__ __forceinline__ void ldmx4(uint32_t& r0, uint32_t& r1, uint32_t& r2,
                                      uint32_t& r3, uint32_t addr) {
    asm volatile("ldmatrix.sync.aligned.m8n8.x4.shared.b16 {%0,%1,%2,%3}, [%4];"
                 : "=r"(r0), "=r"(r1), "=r"(r2), "=r"(r3) : "r"(addr));
}
__device__ __forceinline__ void mma_tf32(float* c, const uint32_t* a,
                                         uint32_t b0, uint32_t b1) {
    asm volatile(
        "mma.sync.aligned.m16n8k8.row.col.f32.tf32.tf32.f32 "
        "{%0,%1,%2,%3}, {%4,%5,%6,%7}, {%8,%9}, {%0,%1,%2,%3};"
        : "+f"(c[0]), "+f"(c[1]), "+f"(c[2]), "+f"(c[3])
        : "r"(a[0]), "r"(a[1]), "r"(a[2]), "r"(a[3]), "r"(b0), "r"(b1));
}
__device__ __forceinline__ void mma_tf32f(float* c, const float* a,
                                          float b0f, float b1f) {
    uint32_t a0 = __float_as_uint(a[0]), a1 = __float_as_uint(a[1]);
    uint32_t a2 = __float_as_uint(a[2]), a3 = __float_as_uint(a[3]);
    uint32_t b0 = __float_as_uint(b0f), b1 = __float_as_uint(b1f);
    asm volatile(
        "mma.sync.aligned.m16n8k8.row.col.f32.tf32.tf32.f32 "
        "{%0,%1,%2,%3}, {%4,%5,%6,%7}, {%8,%9}, {%0,%1,%2,%3};"
        : "+f"(c[0]), "+f"(c[1]), "+f"(c[2]), "+f"(c[3])
        : "r"(a0), "r"(a1), "r"(a2), "r"(a3), "r"(b0), "r"(b1));
}
__device__ __forceinline__ void mma_bf16(float* c, const uint32_t* a,
                                         uint32_t b0, uint32_t b1) {
    asm volatile(
        "mma.sync.aligned.m16n8k16.row.col.f32.bf16.bf16.f32 "
        "{%0,%1,%2,%3}, {%4,%5,%6,%7}, {%8,%9}, {%0,%1,%2,%3};"
        : "+f"(c[0]), "+f"(c[1]), "+f"(c[2]), "+f"(c[3])
        : "r"(a[0]), "r"(a[1]), "r"(a[2]), "r"(a[3]), "r"(b0), "r"(b1));
}
__device__ __forceinline__ void cp16(uint32_t dst, const void* src) {
    asm volatile("cp.async.cg.shared.global [%0], [%1], 16;" :: "r"(dst), "l"(src));
}
__device__ __forceinline__ void cp_commit() {
    asm volatile("cp.async.commit_group;");
}
template <int N>
__device__ __forceinline__ void cp_wait() {
    asm volatile("cp.async.wait_group %0;" :: "n"(N));
}
__device__ __forceinline__ void bsplit(float x, __nv_bfloat16& hi, __nv_bfloat16& lo) {
    hi = __float2bfloat16(x);
    lo = __float2bfloat16(x - __bfloat162float(hi));
}

// ---------------------------------------------------------------------------
// Elementwise tf32 (rna) rounding pass
// ---------------------------------------------------------------------------
__global__ void round_tf32_k(const float4* __restrict__ in, float4* __restrict__ out, int n4)
{
    const int i = blockIdx.x * blockDim.x + threadIdx.x;
    if (i < n4) {
        float4 v = in[i];
        v.x = to_tf32(v.x); v.y = to_tf32(v.y);
        v.z = to_tf32(v.z); v.w = to_tf32(v.w);
        out[i] = v;
    }
}

// ---------------------------------------------------------------------------
// TF32 tensor-core GEMM: C[M,N] = A[M,K] @ W[N,K]^T + bias
// Inputs PRE-ROUNDED to tf32. 128x128 tile, BK=16, 256 threads,
// 3-stage cp.async pipeline, 2 CTAs/SM for latency hiding.
// ---------------------------------------------------------------------------
#define LDA 20
#define BUF_FLOATS (128 * LDA)
#define BUF_BYTES (BUF_FLOATS * 4)

__global__ void __launch_bounds__(256, 2) tf32_gemm_nt(
    const float* __restrict__ A, const float* __restrict__ W,
    const float* __restrict__ bias, float* __restrict__ C,
    int M, int N, int K, int rnd)
{
    __shared__ __align__(16) float As[3][BUF_FLOATS];
    __shared__ __align__(16) float Bs[3][BUF_FLOATS];

    const int bm = blockIdx.y * 128;
    const int bn = blockIdx.x * 128;
    const int tid = threadIdx.x;
    const int lane = tid & 31;
    const int wid = tid >> 5;
    const int wm = wid >> 2;
    const int wn = wid & 3;
    const int g = lane >> 3;
    const int lr = lane & 7;

    const uint32_t sA = (uint32_t)__cvta_generic_to_shared(&As[0][0]);
    const uint32_t sB = (uint32_t)__cvta_generic_to_shared(&Bs[0][0]);

    uint32_t aBase[4], bBase[2];
#pragma unroll
    for (int m = 0; m < 4; m++) {
        int row = wm * 64 + m * 16 + lr + (g & 1) * 8;
        int col = (g >> 1) * 4;
        aBase[m] = sA + (row * LDA + col) * 4;
    }
#pragma unroll
    for (int p = 0; p < 2; p++) {
        int row = wn * 32 + p * 16 + lr + (g >> 1) * 8;
        int col = (g & 1) * 4;
        bBase[p] = sB + (row * LDA + col) * 4;
    }

    const int lrow = tid >> 2;
    const int lcol = (tid & 3) << 2;
    const float* Ap = A + (size_t)(bm + lrow) * K + lcol;
    const float* Wp = W + (size_t)(bn + lrow) * K + lcol;
    const uint32_t smoff = (lrow * LDA + lcol) * 4;
    const uint32_t smoff2 = smoff + 64 * LDA * 4;

    auto issue = [&](int t, int s) {
        const uint32_t da = sA + (uint32_t)s * BUF_BYTES;
        const uint32_t db = sB + (uint32_t)s * BUF_BYTES;
        const float* ap = Ap + t * 16;
        const float* wp = Wp + t * 16;
        cp16(da + smoff, ap);
        cp16(da + smoff2, ap + (size_t)64 * K);
        cp16(db + smoff, wp);
        cp16(db + smoff2, wp + (size_t)64 * K);
        cp_commit();
    };

    float acc[4][4][4];
#pragma unroll
    for (int m = 0; m < 4; m++)
#pragma unroll
        for (int n = 0; n < 4; n++)
#pragma unroll
            for (int i = 0; i < 4; i++) acc[m][n][i] = 0.f;

    const int T = K / 16;
    issue(0, 0);
    issue(1, 1);

    for (int t = 0; t < T; t++) {
        if (t + 1 < T) cp_wait<1>(); else cp_wait<0>();
        __syncthreads();
        if (t + 2 < T) issue(t + 2, (t + 2) % 3);

        const uint32_t bufoff = (uint32_t)(t % 3) * BUF_BYTES;
#pragma unroll
        for (int ks = 0; ks < 16; ks += 8) {
            uint32_t afr[4][4];
#pragma unroll
            for (int m = 0; m < 4; m++)
                ldmx4(afr[m][0], afr[m][1], afr[m][2], afr[m][3],
                      aBase[m] + bufoff + ks * 4);
#pragma unroll
            for (int p = 0; p < 2; p++) {
                uint32_t bf0, bf1, bf2, bf3;
                ldmx4(bf0, bf1, bf2, bf3, bBase[p] + bufoff + ks * 4);
#pragma unroll
                for (int m = 0; m < 4; m++) {
                    mma_tf32(acc[m][2 * p + 0], afr[m], bf0, bf1);
                    mma_tf32(acc[m][2 * p + 1], afr[m], bf2, bf3);
                }
            }
        }
    }

#pragma unroll
    for (int m = 0; m < 4; m++) {
        const int row = bm + wm * 64 + m * 16 + (lane >> 2);
#pragma unroll
        for (int n = 0; n < 4; n++) {
            const int col = bn + wn * 32 + n * 8 + (lane & 3) * 2;
            float bx = 0.f, by = 0.f;
            if (bias) { bx = bias[col]; by = bias[col + 1]; }
            float2 v0 = make_float2(acc[m][n][0] + bx, acc[m][n][1] + by);
            float2 v1 = make_float2(acc[m][n][2] + bx, acc[m][n][3] + by);
            if (rnd) {
                v0.x = to_tf32(v0.x); v0.y = to_tf32(v0.y);
                v1.x = to_tf32(v1.x); v1.y = to_tf32(v1.y);
            }
            *(float2*)&C[(size_t)row * N + col] = v0;
            *(float2*)&C[(size_t)(row + 8) * N + col] = v1;
        }
    }
}

// ---------------------------------------------------------------------------
// RoPE + bf16 hi/lo split. Q additionally prescaled by SCALE_F.
// ---------------------------------------------------------------------------
__global__ void rope_split(const float* __restrict__ Q, const float* __restrict__ K,
                           const float* __restrict__ cosT, const float* __restrict__ sinT,
                           __nv_bfloat16* __restrict__ Qh, __nv_bfloat16* __restrict__ Ql,
                           __nv_bfloat16* __restrict__ Kh, __nv_bfloat16* __restrict__ Kl)
{
    const int idx = blockIdx.x * blockDim.x + threadIdx.x;
    const int d = idx & 63;
    const int h = (idx >> 6) & 31;
    const int s = (idx >> 11) & 2047;
    const int b = idx >> 22;

    const float c1 = cosT[s * 128 + d];
    const float s1 = sinT[s * 128 + d];
    const float c2 = cosT[s * 128 + d + 64];
    const float s2 = sinT[s * 128 + d + 64];

    if (h < 28) {
        const size_t base = (((size_t)b * SEQ + s) * NH + h) * HD;
        const float x1 = Q[base + d];
        const float x2 = Q[base + d + 64];
        const float r1 = (x1 * c1 - x2 * s1) * SCALE_F;
        const float r2 = (x2 * c2 + x1 * s2) * SCALE_F;
        __nv_bfloat16 hi, lo;
        bsplit(r1, hi, lo); Qh[base + d] = hi; Ql[base + d] = lo;
        bsplit(r2, hi, lo); Qh[base + d + 64] = hi; Ql[base + d + 64] = lo;
    } else {
        const size_t base = (((size_t)b * SEQ + s) * NKV + (h - 28)) * HD;
        const float x1 = K[base + d];
        const float x2 = K[base + d + 64];
        const float r1 = x1 * c1 - x2 * s1;
        const float r2 = x2 * c2 + x1 * s2;
        __nv_bfloat16 hi, lo;
        bsplit(r1, hi, lo); Kh[base + d] = hi; Kl[base + d] = lo;
        bsplit(r2, hi, lo); Kh[base + d + 64] = hi; Kl[base + d + 64] = lo;
    }
}

// ---------------------------------------------------------------------------
// Tensor-core causal flash attention (bf16-split QK + tf32 PV).
// Longest-first CTA order: qb = gridDim.x-1-blockIdx.x (tail shrink).
// ---------------------------------------------------------------------------
#define QB 128
#define KB 64
#define FL_QL 34816
#define FL_ST 69632
#define FL_STSZ 69632
#define FL_KL 17408
#define FL_V  34816
#define FL_SMEM 208896
#define LDV 136

__global__ void __launch_bounds__(256, 1) flash_tc(
    const __nv_bfloat16* __restrict__ Qh, const __nv_bfloat16* __restrict__ Ql,
    const __nv_bfloat16* __restrict__ Kh, const __nv_bfloat16* __restrict__ Kl,
    const float* __restrict__ V, float* __restrict__ O)
{
    extern __shared__ char smc[];
    const uint32_t sb = (uint32_t)__cvta_generic_to_shared(smc);

    const int qb = gridDim.x - 1 - blockIdx.x;   // longest-first
    const int h = blockIdx.y, b = blockIdx.z;
    const int kvh = h / NREP;
    const int tid = threadIdx.x;
    const int lane = tid & 31;
    const int w = tid >> 5;
    const int q4 = lane & 3;
    const int r4 = lane >> 2;

    {
        const char* qhg = (const char*)(Qh + (((size_t)b * SEQ + (size_t)qb * QB) * NH + h) * HD);
        const char* qlg = (const char*)(Ql + (((size_t)b * SEQ + (size_t)qb * QB) * NH + h) * HD);
#pragma unroll
        for (int i = 0; i < 16; i++) {
            const int id = tid + i * 256;
            if (id < 2048) {
                const int row = id >> 4, off = (id & 15) * 16;
                cp16(sb + row * 272 + off, qhg + (size_t)row * (NH * HD * 2) + off);
            } else {
                const int id2 = id - 2048;
                const int row = id2 >> 4, off = (id2 & 15) * 16;
                cp16(sb + FL_QL + row * 272 + off, qlg + (size_t)row * (NH * HD * 2) + off);
            }
        }
        cp_commit();
    }

    const char* khg0 = (const char*)(Kh + ((size_t)b * SEQ) * KV_HID + kvh * HD);
    const char* klg0 = (const char*)(Kl + ((size_t)b * SEQ) * KV_HID + kvh * HD);
    const char* vg0  = (const char*)(V + ((size_t)b * SEQ) * KV_HID + kvh * HD);

    auto issue_kv = [&](int kb, int s) {
        const uint32_t stb = sb + FL_ST + (uint32_t)s * FL_STSZ;
        const char* khg = khg0 + (size_t)kb * KB * 1024;
        const char* klg = klg0 + (size_t)kb * KB * 1024;
        const char* vg  = vg0 + (size_t)kb * KB * 2048;
#pragma unroll
        for (int i = 0; i < 16; i++) {
            const int id = tid + i * 256;
            if (id < 1024) {
                const int row = id >> 4, off = (id & 15) * 16;
                cp16(stb + row * 272 + off, khg + (size_t)row * 1024 + off);
            } else if (id < 2048) {
                const int id2 = id - 1024;
                const int row = id2 >> 4, off = (id2 & 15) * 16;
                cp16(stb + FL_KL + row * 272 + off, klg + (size_t)row * 1024 + off);
            } else {
                const int id2 = id - 2048;
                const int row = id2 >> 5, off = (id2 & 31) * 16;
                cp16(stb + FL_V + row * 544 + off, vg + (size_t)row * 2048 + off);
            }
        }
        cp_commit();
    };

    const int kbmax = 2 * qb + 1;
    issue_kv(0, 0);
    issue_kv(1, 1);

    float oacc[16][4];
#pragma unroll
    for (int i = 0; i < 16; i++)
#pragma unroll
        for (int c = 0; c < 4; c++) oacc[i][c] = 0.f;
    float m0 = -1e30f, m1 = -1e30f, l0 = 0.f, l1 = 0.f;

    const int arow = w * 16 + r4;
    const int rg0 = qb * QB + arow;
    const int rg1 = rg0 + 8;

    const char* aH = smc + arow * 272 + q4 * 4;
    const char* aL = smc + FL_QL + arow * 272 + q4 * 4;

    for (int kb = 0; kb <= kbmax; kb++) {
        if (kb < kbmax) cp_wait<1>(); else cp_wait<0>();
        __syncthreads();

        const int cur = kb & 1;
        const char* Khp = smc + FL_ST + (size_t)cur * FL_STSZ;
        const char* Klp = Khp + FL_KL;
        const float* Vsp = (const float*)(Khp + FL_V);

        float sacc[8][4];
#pragma unroll
        for (int nt = 0; nt < 8; nt++)
#pragma unroll
            for (int c = 0; c < 4; c++) sacc[nt][c] = 0.f;

#pragma unroll
        for (int kt = 0; kt < 8; kt++) {
            const int ko = kt * 32;
            uint32_t ah[4], al[4];
            ah[0] = *(const uint32_t*)(aH + ko);
            ah[1] = *(const uint32_t*)(aH + ko + 8 * 272);
            ah[2] = *(const uint32_t*)(aH + ko + 16);
            ah[3] = *(const uint32_t*)(aH + ko + 8 * 272 + 16);
            al[0] = *(const uint32_t*)(aL + ko);
            al[1] = *(const uint32_t*)(aL + ko + 8 * 272);
            al[2] = *(const uint32_t*)(aL + ko + 16);
            al[3] = *(const uint32_t*)(aL + ko + 8 * 272 + 16);
#pragma unroll
            for (int nt = 0; nt < 8; nt++) {
                const char* bp = Khp + (nt * 8 + r4) * 272 + q4 * 4 + ko;
                const char* bq = Klp + (nt * 8 + r4) * 272 + q4 * 4 + ko;
                const uint32_t bh0 = *(const uint32_t*)bp;
                const uint32_t bh1 = *(const uint32_t*)(bp + 16);
                const uint32_t bl0 = *(const uint32_t*)bq;
                const uint32_t bl1 = *(const uint32_t*)(bq + 16);
                mma_bf16(sacc[nt], ah, bh0, bh1);
                mma_bf16(sacc[nt], al, bh0, bh1);
                mma_bf16(sacc[nt], ah, bl0, bl1);
            }
        }

        if (kb >= 2 * qb) {
            const int colb = kb * KB + 2 * q4;
#pragma unroll
            for (int nt = 0; nt < 8; nt++) {
                const int c0 = colb + nt * 8;
                if (c0 > rg0)     sacc[nt][0] = -1e30f;
                if (c0 + 1 > rg0) sacc[nt][1] = -1e30f;
                if (c0 > rg1)     sacc[nt][2] = -1e30f;
                if (c0 + 1 > rg1) sacc[nt][3] = -1e30f;
            }
        }
        float mb0 = -1e30f, mb1 = -1e30f;
#pragma unroll
        for (int nt = 0; nt < 8; nt++) {
            mb0 = fmaxf(mb0, fmaxf(sacc[nt][0], sacc[nt][1]));
            mb1 = fmaxf(mb1, fmaxf(sacc[nt][2], sacc[nt][3]));
        }
        mb0 = fmaxf(mb0, __shfl_xor_sync(0xffffffffu, mb0, 1));
        mb0 = fmaxf(mb0, __shfl_xor_sync(0xffffffffu, mb0, 2));
        mb1 = fmaxf(mb1, __shfl_xor_sync(0xffffffffu, mb1, 1));
        mb1 = fmaxf(mb1, __shfl_xor_sync(0xffffffffu, mb1, 2));

        const float mn0 = fmaxf(m0, mb0), mn1 = fmaxf(m1, mb1);
        const float a0 = __expf(m0 - mn0), a1 = __expf(m1 - mn1);
        m0 = mn0; m1 = mn1;

        float ls0 = 0.f, ls1 = 0.f;
#pragma unroll
        for (int nt = 0; nt < 8; nt++) {
            float p0 = to_tf32(__expf(sacc[nt][0] - mn0));
            float p1 = to_tf32(__expf(sacc[nt][1] - mn0));
            float p2 = to_tf32(__expf(sacc[nt][2] - mn1));
            float p3 = to_tf32(__expf(sacc[nt][3] - mn1));
            sacc[nt][0] = p0; sacc[nt][1] = p1;
            sacc[nt][2] = p2; sacc[nt][3] = p3;
            ls0 += p0 + p1; ls1 += p2 + p3;
        }
        ls0 += __shfl_xor_sync(0xffffffffu, ls0, 1);
        ls0 += __shfl_xor_sync(0xffffffffu, ls0, 2);
        ls1 += __shfl_xor_sync(0xffffffffu, ls1, 1);
        ls1 += __shfl_xor_sync(0xffffffffu, ls1, 2);
        l0 = l0 * a0 + ls0;
        l1 = l1 * a1 + ls1;

#pragma unroll
        for (int nt2 = 0; nt2 < 16; nt2++) {
            oacc[nt2][0] *= a0; oacc[nt2][1] *= a0;
            oacc[nt2][2] *= a1; oacc[nt2][3] *= a1;
        }

        const int src0 = (lane & ~3) | (q4 >> 1);
        const int src1 = src0 | 2;
        const bool oddq = (q4 & 1);
#pragma unroll
        for (int kt2 = 0; kt2 < 8; kt2++) {
            const float t00 = __shfl_sync(0xffffffffu, sacc[kt2][0], src0);
            const float t01 = __shfl_sync(0xffffffffu, sacc[kt2][1], src0);
            const float t02 = __shfl_sync(0xffffffffu, sacc[kt2][2], src0);
            const float t03 = __shfl_sync(0xffffffffu, sacc[kt2][3], src0);
            const float t10 = __shfl_sync(0xffffffffu, sacc[kt2][0], src1);
            const float t11 = __shfl_sync(0xffffffffu, sacc[kt2][1], src1);
            const float t12 = __shfl_sync(0xffffffffu, sacc[kt2][2], src1);
            const float t13 = __shfl_sync(0xffffffffu, sacc[kt2][3], src1);
            float pa[4];
            pa[0] = oddq ? t01 : t00;
            pa[1] = oddq ? t03 : t02;
            pa[2] = oddq ? t11 : t10;
            pa[3] = oddq ? t13 : t12;
            const float* vrow = Vsp + (kt2 * 8 + q4) * LDV + r4;
#pragma unroll
            for (int nt2 = 0; nt2 < 16; nt2++) {
                mma_tf32f(oacc[nt2], pa, vrow[nt2 * 8], vrow[nt2 * 8 + 4 * LDV]);
            }
        }

        __syncthreads();
        if (kb + 2 <= kbmax) issue_kv(kb + 2, cur);
    }

    const float inv0 = 1.f / l0, inv1 = 1.f / l1;
    float* o0 = O + (((size_t)b * SEQ + rg0) * NH + h) * HD;
    float* o1 = O + (((size_t)b * SEQ + rg1) * NH + h) * HD;
#pragma unroll
    for (int nt2 = 0; nt2 < 16; nt2++) {
        const int col = nt2 * 8 + 2 * q4;
        *(float2*)(o0 + col) = make_float2(to_tf32(oacc[nt2][0] * inv0),
                                           to_tf32(oacc[nt2][1] * inv0));
        *(float2*)(o1 + col) = make_float2(to_tf32(oacc[nt2][2] * inv1),
                                           to_tf32(oacc[nt2][3] * inv1));
    }
}

// ---------------------------------------------------------------------------
extern "C" void kernel_launch(void* const* d_in, const int* in_sizes, int n_in,
                              void* d_out, int out_size)
{
    const float* hs   = (const float*)d_in[0];
    const float* cosT = (const float*)d_in[1];
    const float* sinT = (const float*)d_in[2];
    const float* q_w = (const float*)d_in[4];
    const float* q_b = (const float*)d_in[5];
    const float* k_w = (const float*)d_in[6];
    const float* k_b = (const float*)d_in[7];
    const float* v_w = (const float*)d_in[8];
    const float* v_b = (const float*)d_in[9];
    const float* o_w = (const float*)d_in[10];
    float* out = (float*)d_out;

    float *Qb, *Kb, *Vb, *Ab, *HSr, *QWr, *KWr, *VWr, *OWr;
    __nv_bfloat16 *Qhi, *Qlo, *Khi, *Klo;
    cudaGetSymbolAddress((void**)&Qb, g_Q);
    cudaGetSymbolAddress((void**)&Kb, g_K);
    cudaGetSymbolAddress((void**)&Vb, g_V);
    cudaGetSymbolAddress((void**)&Ab, g_A);
    cudaGetSymbolAddress((void**)&HSr, g_HSr);
    cudaGetSymbolAddress((void**)&QWr, g_QWr);
    cudaGetSymbolAddress((void**)&KWr, g_KWr);
    cudaGetSymbolAddress((void**)&VWr, g_VWr);
    cudaGetSymbolAddress((void**)&OWr, g_OWr);
    cudaGetSymbolAddress((void**)&Qhi, g_Qhi);
    cudaGetSymbolAddress((void**)&Qlo, g_Qlo);
    cudaGetSymbolAddress((void**)&Khi, g_Khi);
    cudaGetSymbolAddress((void**)&Klo, g_Klo);

    static cudaStream_t sK = nullptr, sV = nullptr;
    static cudaEvent_t eFork = nullptr, eHS = nullptr, eQW = nullptr,
                       eK = nullptr, eV = nullptr, eOW = nullptr;
    if (!sK) {
        cudaStreamCreateWithFlags(&sK, cudaStreamNonBlocking);
        cudaStreamCreateWithFlags(&sV, cudaStreamNonBlocking);
        cudaEventCreateWithFlags(&eFork, cudaEventDisableTiming);
        cudaEventCreateWithFlags(&eHS, cudaEventDisableTiming);
        cudaEventCreateWithFlags(&eQW, cudaEventDisableTiming);
        cudaEventCreateWithFlags(&eK, cudaEventDisableTiming);
        cudaEventCreateWithFlags(&eV, cudaEventDisableTiming);
        cudaEventCreateWithFlags(&eOW, cudaEventDisableTiming);
        cudaFuncSetAttribute(flash_tc, cudaFuncAttributeMaxDynamicSharedMemorySize, FL_SMEM);
    }

    const int nt = 256;

    // Fork FIRST: capture-legal — side streams join via event from origin stream.
    cudaEventRecord(eFork, 0);
    cudaStreamWaitEvent(sK, eFork, 0);
    cudaStreamWaitEvent(sV, eFork, 0);

    // sK: round QW -> signal; round KW (K-proj waits on eHS below)
    {
        const int n4q = HID * HID / 4;
        round_tf32_k<<<(n4q + nt - 1) / nt, nt, 0, sK>>>((const float4*)q_w, (float4*)QWr, n4q);
        cudaEventRecord(eQW, sK);
        const int n4k = KV_HID * HID / 4;
        round_tf32_k<<<(n4k + nt - 1) / nt, nt, 0, sK>>>((const float4*)k_w, (float4*)KWr, n4k);
    }

    // sV: round VW
    {
        const int n4v = KV_HID * HID / 4;
        round_tf32_k<<<(n4v + nt - 1) / nt, nt, 0, sV>>>((const float4*)v_w, (float4*)VWr, n4v);
    }

    // main: round HS (everyone needs it)
    {
        const int n4 = M_ROWS * HID / 4;
        round_tf32_k<<<(n4 + nt - 1) / nt, nt>>>((const float4*)hs, (float4*)HSr, n4);
        cudaEventRecord(eHS, 0);
    }
    cudaStreamWaitEvent(sK, eHS, 0);
    cudaStreamWaitEvent(sV, eHS, 0);

    // main: Q-proj (needs QW)
    cudaStreamWaitEvent(0, eQW, 0);
    tf32_gemm_nt<<<dim3(HID / 128, M_ROWS / 128), 256, 0, 0>>>(
        HSr, QWr, q_b, Qb, M_ROWS, HID, HID, 0);

    // sK: K-proj
    tf32_gemm_nt<<<dim3(KV_HID / 128, M_ROWS / 128), 256, 0, sK>>>(
        HSr, KWr, k_b, Kb, M_ROWS, KV_HID, HID, 0);
    cudaEventRecord(eK, sK);

    // sV: V-proj (tf32-rounded output), then round OW (overlaps rope+flash)
    tf32_gemm_nt<<<dim3(KV_HID / 128, M_ROWS / 128), 256, 0, sV>>>(
        HSr, VWr, v_b, Vb, M_ROWS, KV_HID, HID, 1);
    cudaEventRecord(eV, sV);
    {
        const int n4 = HID * HID / 4;
        round_tf32_k<<<(n4 + nt - 1) / nt, nt, 0, sV>>>((const float4*)o_w, (float4*)OWr, n4);
    }
    cudaEventRecord(eOW, sV);

    // Join K,V for rope
    cudaStreamWaitEvent(0, eK, 0);
    cudaStreamWaitEvent(0, eV, 0);

    // RoPE + bf16 hi/lo split
    rope_split<<<(BATCH * SEQ * 32 * 64) / 256, 256>>>(
        Qb, Kb, cosT, sinT, Qhi, Qlo, Khi, Klo);

    // Flash attention (epilogue writes tf32-rounded A)
    flash_tc<<<dim3(SEQ / QB, NH, BATCH), 256, FL_SMEM>>>(
        Qhi, Qlo, Khi, Klo, Vb, Ab);

    // Output projection
    cudaStreamWaitEvent(0, eOW, 0);
    tf32_gemm_nt<<<dim3(HID / 128, M_ROWS / 128), 256>>>(
        Ab, OWr, nullptr, out, M_ROWS, HID, HID, 0);
}